// round 15
// baseline (speedup 1.0000x reference)
#include <cuda_runtime.h>
#include <cstdint>

#define NSN 50000
#define NDN 50000
#define EE  600000
#define CC  64
#define HH  8
#define LNEPS 1e-5f

typedef unsigned long long u64;

// packed f32x2 helpers (SASS FFMA2 — only reachable via PTX fma.rn.f32x2)
#define FFMA2(d, a, b, c) asm("fma.rn.f32x2 %0, %1, %2, %3;" : "=l"(d) : "l"(a), "l"(b), "l"(c))
#define MUL2(d, a, b)     asm("mul.rn.f32x2 %0, %1, %2;"     : "=l"(d) : "l"(a), "l"(b))
#define ADD2(d, a, b)     asm("add.rn.f32x2 %0, %1, %2;"     : "=l"(d) : "l"(a), "l"(b))
#define PK2(d, x)         asm("mov.b64 %0, {%1, %1};"        : "=l"(d) : "f"(x))
#define UPK2(lo, hi, v)   asm("mov.b64 {%0, %1}, %2;"        : "=f"(lo), "=f"(hi) : "l"(v))

// ---------------- scratch ----------------
__device__ float g_ms[(size_t)NSN*CC];
__device__ float g_md[(size_t)NDN*CC];
__device__ float g_z[(size_t)NDN*HH];
__device__ float g_acc[(size_t)NDN*CC];
__device__ unsigned g_ctrE;
__device__ unsigned g_ctrF;

// ---------------- node projections: 512 threads, 128-node tiles, 2n x 8c ----------------
// Also zeroes g_acc / g_z for dst tiles and resets dynamic-tile counters.
#define KN_SMEM 16960
#define SDN 132
__global__ void __launch_bounds__(512)
k_node(const float* __restrict__ src_f, const float* __restrict__ dst_f,
       const float* __restrict__ lnsw, const float* __restrict__ lnsb,
       const float* __restrict__ Wsrc,
       const float* __restrict__ lndw, const float* __restrict__ lndb,
       const float* __restrict__ Wdst, const float* __restrict__ bdst) {
    extern __shared__ float sn[];
    float* sW  = sn;
    float* sYt = sn + 8192;
    float* sBd = sn + 16640;
    float* sLn = sn + 16704;
    const int tid = threadIdx.x;
    if (blockIdx.x == 0 && tid == 0) { g_ctrE = 0u; g_ctrF = 0u; }
    for (int i = tid; i < 8192; i += 512) sW[i] = (i < 4096) ? Wsrc[i] : Wdst[i-4096];
    if (tid < 64) {
        sBd[tid] = bdst[tid];
        sLn[tid] = lnsw[tid]; sLn[64+tid] = lnsb[tid];
        sLn[128+tid] = lndw[tid]; sLn[192+tid] = lndb[tid];
    }
    const int NTS = (NSN + 127)/128, NTD = (NDN + 127)/128;
    const int lane = tid & 31, warp = tid >> 5;
    const int tc = warp & 7;
    const int n0 = ((warp >> 3) << 6) + lane*2;
    for (int tile = blockIdx.x; tile < NTS + NTD; tile += gridDim.x) {
        const bool isd = (tile >= NTS);
        const int base = (isd ? tile - NTS : tile) * 128;
        const int NV = isd ? NDN : NSN;
        __syncthreads();
        {
            const int n = tid >> 2, p = tid & 3;
            int gn = base + n; if (gn >= NV) gn = NV - 1;
            const float4* xr = (const float4*)((isd ? dst_f : src_f) + (size_t)gn*64 + p*16);
            float4 v[4]; float s = 0.f, q = 0.f;
            #pragma unroll
            for (int j = 0; j < 4; j++) {
                v[j] = xr[j];
                s += v[j].x + v[j].y + v[j].z + v[j].w;
                q += v[j].x*v[j].x + v[j].y*v[j].y + v[j].z*v[j].z + v[j].w*v[j].w;
            }
            s += __shfl_xor_sync(~0u, s, 1); s += __shfl_xor_sync(~0u, s, 2);
            q += __shfl_xor_sync(~0u, q, 1); q += __shfl_xor_sync(~0u, q, 2);
            const float mean = s * (1.0f/64.0f);
            const float var  = q * (1.0f/64.0f) - mean*mean;
            const float rs   = rsqrtf(var + LNEPS);
            const float* lw = sLn + (isd ? 128 : 0);
            const float* lb = sLn + (isd ? 192 : 64);
            #pragma unroll
            for (int j = 0; j < 4; j++) {
                const int k0 = p*16 + j*4;
                sYt[(k0+0)*SDN + n] = (v[j].x - mean)*rs*lw[k0+0] + lb[k0+0];
                sYt[(k0+1)*SDN + n] = (v[j].y - mean)*rs*lw[k0+1] + lb[k0+1];
                sYt[(k0+2)*SDN + n] = (v[j].z - mean)*rs*lw[k0+2] + lb[k0+2];
                sYt[(k0+3)*SDN + n] = (v[j].w - mean)*rs*lw[k0+3] + lb[k0+3];
            }
            if (isd && base + n < NDN) {
                float4 z = make_float4(0.f, 0.f, 0.f, 0.f);
                *(float4*)(g_acc + (size_t)(base + n)*64 + p*16)      = z;
                *(float4*)(g_acc + (size_t)(base + n)*64 + p*16 + 4)  = z;
                *(float4*)(g_acc + (size_t)(base + n)*64 + p*16 + 8)  = z;
                *(float4*)(g_acc + (size_t)(base + n)*64 + p*16 + 12) = z;
                *(float2*)(g_z + (size_t)(base + n)*8 + p*2) = make_float2(0.f, 0.f);
            }
        }
        __syncthreads();
        {
            const float* W = sW + (isd ? 4096 : 0);
            u64 acc[2][4] = {};
            #pragma unroll 4
            for (int k = 0; k < 64; k++) {
                float2 xv = *(const float2*)(sYt + k*SDN + n0);
                ulonglong2 wa = *(const ulonglong2*)(W + k*64 + tc*8);
                ulonglong2 wb = *(const ulonglong2*)(W + k*64 + tc*8 + 4);
                u64 xp;
                PK2(xp, xv.x);
                FFMA2(acc[0][0], xp, wa.x, acc[0][0]); FFMA2(acc[0][1], xp, wa.y, acc[0][1]);
                FFMA2(acc[0][2], xp, wb.x, acc[0][2]); FFMA2(acc[0][3], xp, wb.y, acc[0][3]);
                PK2(xp, xv.y);
                FFMA2(acc[1][0], xp, wa.x, acc[1][0]); FFMA2(acc[1][1], xp, wa.y, acc[1][1]);
                FFMA2(acc[1][2], xp, wb.x, acc[1][2]); FFMA2(acc[1][3], xp, wb.y, acc[1][3]);
            }
            float* outp = isd ? g_md : g_ms;
            #pragma unroll
            for (int i = 0; i < 2; i++) {
                const int gn = base + n0 + i;
                if (gn >= NV) continue;
                float4 o0, o1;
                UPK2(o0.x, o0.y, acc[i][0]); UPK2(o0.z, o0.w, acc[i][1]);
                UPK2(o1.x, o1.y, acc[i][2]); UPK2(o1.z, o1.w, acc[i][3]);
                if (isd) {
                    o0.x += sBd[tc*8+0]; o0.y += sBd[tc*8+1];
                    o0.z += sBd[tc*8+2]; o0.w += sBd[tc*8+3];
                    o1.x += sBd[tc*8+4]; o1.y += sBd[tc*8+5];
                    o1.z += sBd[tc*8+6]; o1.w += sBd[tc*8+7];
                }
                *(float4*)(outp + (size_t)gn*64 + tc*8)     = o0;
                *(float4*)(outp + (size_t)gn*64 + tc*8 + 4) = o1;
            }
        }
    }
}

// ---------------- heavy fused edge kernel: 256 threads, 4e x 16c strips, dynamic tiles ----------------
#define TEDGE 128
#define NTILE2 ((EE + TEDGE - 1) / TEDGE)
#define SDE 132
#define OFF_WR1   0
#define OFF_WR2   4096
#define OFF_WEA   12288
#define OFF_WDTP  13312
#define OFF_BR1   21504
#define OFF_BR2   21568
#define OFF_AL    21696
#define OFF_ESt   21760
#define OFF_Rt    (OFF_ESt + 8448)
#define OFF_MSGt  (OFF_Rt  + 8448)
#define OFF_EAt   (OFF_MSGt+ 8448)
#define SMEM_EDGE_FLOATS (OFF_EAt + 2112)

__global__ void __launch_bounds__(256, 1)
k_edge(const float* __restrict__ es_g, const float* __restrict__ ea_g,
       const float* __restrict__ el_g,
       const int* __restrict__ esrc, const int* __restrict__ edst,
       const float* __restrict__ Wr1, const float* __restrict__ br1,
       const float* __restrict__ Wr2, const float* __restrict__ br2,
       const float* __restrict__ Wea, const float* __restrict__ Wdtp,
       const float* __restrict__ alpha) {
    extern __shared__ float sm[];
    __shared__ int s_tile;
    float* sWr1  = sm + OFF_WR1;
    float* sWr2  = sm + OFF_WR2;
    float* sWea  = sm + OFF_WEA;
    float* sWdtp = sm + OFF_WDTP;
    float* sbr1  = sm + OFF_BR1;
    float* sbr2  = sm + OFF_BR2;
    float* sal   = sm + OFF_AL;
    float* sESt  = sm + OFF_ESt;
    float* sRt   = sm + OFF_Rt;
    float* sMSGt = sm + OFF_MSGt;
    float* sEAt  = sm + OFF_EAt;

    const int tid = threadIdx.x;
    for (int i = tid; i < 4096; i += 256) sWr1[i]  = Wr1[i];
    for (int i = tid; i < 8192; i += 256) sWr2[i]  = Wr2[i];
    for (int i = tid; i < 1024; i += 256) sWea[i]  = Wea[i];
    for (int i = tid; i < 8192; i += 256) sWdtp[i] = Wdtp[i];
    if (tid < 64)  sbr1[tid] = br1[tid];
    if (tid < 128) sbr2[tid] = br2[tid];
    if (tid < 64)  sal[tid]  = alpha[tid];

    const int te = tid & 31;
    const int tc = tid >> 5;     // warp = head; logit strip [tc*8,+8), val strip [64+tc*8,+8)
    const int e0 = te * 4;

    while (true) {
        if (tid == 0) s_tile = (int)atomicAdd(&g_ctrE, 1u);
        __syncthreads();   // covers weight staging on first iter; prior tile consumed
        const int tile = s_tile;
        if (tile >= NTILE2) break;
        const int base = tile * TEDGE;

        // ---- stage: ES^T, MSG^T (gather), EA^T ----
        {
            #pragma unroll
            for (int j = 0; j < 2; j++) {
                const int idx = tid + j*256;
                const int e = idx >> 2, p = idx & 3;
                int ge = base + e; if (ge >= EE) ge = EE - 1;
                const float4* esrow = (const float4*)(es_g + (size_t)ge*64 + p*16);
                const int sidx = esrc[ge], didx = edst[ge];
                const float4* msr = (const float4*)(g_ms + (size_t)sidx*64 + p*16);
                const float4* mdr = (const float4*)(g_md + (size_t)didx*64 + p*16);
                #pragma unroll
                for (int q = 0; q < 4; q++) {
                    float4 v = esrow[q];
                    int k0 = p*16 + q*4;
                    sESt[(k0+0)*SDE + e] = v.x;
                    sESt[(k0+1)*SDE + e] = v.y;
                    sESt[(k0+2)*SDE + e] = v.z;
                    sESt[(k0+3)*SDE + e] = v.w;
                    float4 a = msr[q], d = mdr[q];
                    sMSGt[(k0+0)*SDE + e] = a.x + d.x;
                    sMSGt[(k0+1)*SDE + e] = a.y + d.y;
                    sMSGt[(k0+2)*SDE + e] = a.z + d.z;
                    sMSGt[(k0+3)*SDE + e] = a.w + d.w;
                }
            }
            if (tid < TEDGE) {
                int ge2 = base + tid; if (ge2 >= EE) ge2 = EE - 1;
                const float4* ear = (const float4*)(ea_g + (size_t)ge2*16);
                #pragma unroll
                for (int q = 0; q < 4; q++) {
                    float4 v = ear[q];
                    sEAt[(q*4+0)*SDE + tid] = v.x;
                    sEAt[(q*4+1)*SDE + tid] = v.y;
                    sEAt[(q*4+2)*SDE + tid] = v.z;
                    sEAt[(q*4+3)*SDE + tid] = v.w;
                }
            }
        }
        __syncthreads();

        // ---- GEMM1 + Gea + T (cols tc*8..+8 of 64) ----
        u64 ea2[4][4] = {};
        {
            u64 acc[4][4] = {};
            #pragma unroll 4
            for (int k = 0; k < 64; k++) {
                float4 xv = *(const float4*)(sESt + k*SDE + e0);
                ulonglong2 wa = *(const ulonglong2*)(sWr1 + k*64 + tc*8);
                ulonglong2 wb = *(const ulonglong2*)(sWr1 + k*64 + tc*8 + 4);
                u64 xp;
                PK2(xp, xv.x);
                FFMA2(acc[0][0], xp, wa.x, acc[0][0]); FFMA2(acc[0][1], xp, wa.y, acc[0][1]);
                FFMA2(acc[0][2], xp, wb.x, acc[0][2]); FFMA2(acc[0][3], xp, wb.y, acc[0][3]);
                PK2(xp, xv.y);
                FFMA2(acc[1][0], xp, wa.x, acc[1][0]); FFMA2(acc[1][1], xp, wa.y, acc[1][1]);
                FFMA2(acc[1][2], xp, wb.x, acc[1][2]); FFMA2(acc[1][3], xp, wb.y, acc[1][3]);
                PK2(xp, xv.z);
                FFMA2(acc[2][0], xp, wa.x, acc[2][0]); FFMA2(acc[2][1], xp, wa.y, acc[2][1]);
                FFMA2(acc[2][2], xp, wb.x, acc[2][2]); FFMA2(acc[2][3], xp, wb.y, acc[2][3]);
                PK2(xp, xv.w);
                FFMA2(acc[3][0], xp, wa.x, acc[3][0]); FFMA2(acc[3][1], xp, wa.y, acc[3][1]);
                FFMA2(acc[3][2], xp, wb.x, acc[3][2]); FFMA2(acc[3][3], xp, wb.y, acc[3][3]);
            }
            #pragma unroll
            for (int jp = 0; jp < 4; jp++) {
                float lo[4], hi[4];
                #pragma unroll
                for (int i = 0; i < 4; i++) UPK2(lo[i], hi[i], acc[i][jp]);
                float b0 = sbr1[tc*8 + 2*jp], b1 = sbr1[tc*8 + 2*jp + 1];
                float4 v0, v1;
                v0.x = lo[0]+b0; v0.y = lo[1]+b0; v0.z = lo[2]+b0; v0.w = lo[3]+b0;
                v1.x = hi[0]+b1; v1.y = hi[1]+b1; v1.z = hi[2]+b1; v1.w = hi[3]+b1;
                v0.x /= (1.0f + __expf(-v0.x)); v0.y /= (1.0f + __expf(-v0.y));
                v0.z /= (1.0f + __expf(-v0.z)); v0.w /= (1.0f + __expf(-v0.w));
                v1.x /= (1.0f + __expf(-v1.x)); v1.y /= (1.0f + __expf(-v1.y));
                v1.z /= (1.0f + __expf(-v1.z)); v1.w /= (1.0f + __expf(-v1.w));
                *(float4*)(sRt + (tc*8 + 2*jp)*SDE   + e0) = v0;
                *(float4*)(sRt + (tc*8 + 2*jp+1)*SDE + e0) = v1;
            }
            #pragma unroll
            for (int k = 0; k < 16; k++) {
                float4 xv = *(const float4*)(sEAt + k*SDE + e0);
                ulonglong2 wa = *(const ulonglong2*)(sWea + k*64 + tc*8);
                ulonglong2 wb = *(const ulonglong2*)(sWea + k*64 + tc*8 + 4);
                u64 xp;
                PK2(xp, xv.x);
                FFMA2(ea2[0][0], xp, wa.x, ea2[0][0]); FFMA2(ea2[0][1], xp, wa.y, ea2[0][1]);
                FFMA2(ea2[0][2], xp, wb.x, ea2[0][2]); FFMA2(ea2[0][3], xp, wb.y, ea2[0][3]);
                PK2(xp, xv.y);
                FFMA2(ea2[1][0], xp, wa.x, ea2[1][0]); FFMA2(ea2[1][1], xp, wa.y, ea2[1][1]);
                FFMA2(ea2[1][2], xp, wb.x, ea2[1][2]); FFMA2(ea2[1][3], xp, wb.y, ea2[1][3]);
                PK2(xp, xv.z);
                FFMA2(ea2[2][0], xp, wa.x, ea2[2][0]); FFMA2(ea2[2][1], xp, wa.y, ea2[2][1]);
                FFMA2(ea2[2][2], xp, wb.x, ea2[2][2]); FFMA2(ea2[2][3], xp, wb.y, ea2[2][3]);
                PK2(xp, xv.w);
                FFMA2(ea2[3][0], xp, wa.x, ea2[3][0]); FFMA2(ea2[3][1], xp, wa.y, ea2[3][1]);
                FFMA2(ea2[3][2], xp, wb.x, ea2[3][2]); FFMA2(ea2[3][3], xp, wb.y, ea2[3][3]);
            }
            #pragma unroll
            for (int jp = 0; jp < 4; jp++) {
                #pragma unroll
                for (int h = 0; h < 2; h++) {
                    const int c = tc*8 + 2*jp + h;
                    float4 m4 = *(float4*)(sMSGt + c*SDE + e0);
                    float v0, v1, v2, v3, dummy;
                    if (h == 0) {
                        UPK2(v0, dummy, ea2[0][jp]); UPK2(v1, dummy, ea2[1][jp]);
                        UPK2(v2, dummy, ea2[2][jp]); UPK2(v3, dummy, ea2[3][jp]);
                    } else {
                        UPK2(dummy, v0, ea2[0][jp]); UPK2(dummy, v1, ea2[1][jp]);
                        UPK2(dummy, v2, ea2[2][jp]); UPK2(dummy, v3, ea2[3][jp]);
                    }
                    m4.x *= v0; m4.y *= v1; m4.z *= v2; m4.w *= v3;
                    *(float4*)(sMSGt + c*SDE + e0) = m4;
                }
            }
        }
        __syncthreads();

        // ---- GEMM2: w_edge, strips [tc*8,+8) and [64+tc*8,+8) ----
        u64 we[4][8];
        {
            u64 acc[4][8] = {};
            #pragma unroll 2
            for (int k = 0; k < 64; k++) {
                float4 xv = *(const float4*)(sRt + k*SDE + e0);
                const float* wrow = sWr2 + k*128;
                ulonglong2 wa = *(const ulonglong2*)(wrow + tc*8);
                ulonglong2 wb = *(const ulonglong2*)(wrow + tc*8 + 4);
                ulonglong2 wc = *(const ulonglong2*)(wrow + 64 + tc*8);
                ulonglong2 wd = *(const ulonglong2*)(wrow + 64 + tc*8 + 4);
                u64 xp;
                #pragma unroll
                for (int i = 0; i < 4; i++) {
                    float x = (i==0) ? xv.x : (i==1) ? xv.y : (i==2) ? xv.z : xv.w;
                    PK2(xp, x);
                    FFMA2(acc[i][0], xp, wa.x, acc[i][0]); FFMA2(acc[i][1], xp, wa.y, acc[i][1]);
                    FFMA2(acc[i][2], xp, wb.x, acc[i][2]); FFMA2(acc[i][3], xp, wb.y, acc[i][3]);
                    FFMA2(acc[i][4], xp, wc.x, acc[i][4]); FFMA2(acc[i][5], xp, wc.y, acc[i][5]);
                    FFMA2(acc[i][6], xp, wd.x, acc[i][6]); FFMA2(acc[i][7], xp, wd.y, acc[i][7]);
                }
            }
            #pragma unroll
            for (int i = 0; i < 4; i++) {
                #pragma unroll
                for (int jp = 0; jp < 4; jp++) {
                    u64 bA = *(const u64*)(sbr2 + tc*8 + 2*jp);
                    u64 bB = *(const u64*)(sbr2 + 64 + tc*8 + 2*jp);
                    ADD2(we[i][jp],   acc[i][jp],   bA);
                    ADD2(we[i][jp+4], acc[i][jp+4], bB);
                }
            }
        }

        // ---- GEMM3: dtp, same strips ----
        u64 dtp[4][8];
        {
            u64 acc[4][8] = {};
            #pragma unroll 2
            for (int k = 0; k < 64; k++) {
                float4 xv = *(const float4*)(sMSGt + k*SDE + e0);
                const float* wrow = sWdtp + k*128;
                ulonglong2 wa = *(const ulonglong2*)(wrow + tc*8);
                ulonglong2 wb = *(const ulonglong2*)(wrow + tc*8 + 4);
                ulonglong2 wc = *(const ulonglong2*)(wrow + 64 + tc*8);
                ulonglong2 wd = *(const ulonglong2*)(wrow + 64 + tc*8 + 4);
                u64 xp;
                #pragma unroll
                for (int i = 0; i < 4; i++) {
                    float x = (i==0) ? xv.x : (i==1) ? xv.y : (i==2) ? xv.z : xv.w;
                    PK2(xp, x);
                    FFMA2(acc[i][0], xp, wa.x, acc[i][0]); FFMA2(acc[i][1], xp, wa.y, acc[i][1]);
                    FFMA2(acc[i][2], xp, wb.x, acc[i][2]); FFMA2(acc[i][3], xp, wb.y, acc[i][3]);
                    FFMA2(acc[i][4], xp, wc.x, acc[i][4]); FFMA2(acc[i][5], xp, wc.y, acc[i][5]);
                    FFMA2(acc[i][6], xp, wd.x, acc[i][6]); FFMA2(acc[i][7], xp, wd.y, acc[i][7]);
                }
            }
            #pragma unroll
            for (int i = 0; i < 4; i++)
                #pragma unroll
                for (int jp = 0; jp < 8; jp++)
                    MUL2(dtp[i][jp], acc[i][jp], we[i][jp]);
        }

        // ---- fused epilogue: warp owns head tc end-to-end ----
        #pragma unroll
        for (int i = 0; i < 4; i++) {
            const int ge = base + e0 + i;
            if (ge >= EE) continue;
            float lg = 0.0f;
            #pragma unroll
            for (int jp = 0; jp < 4; jp++) {
                float x0, x1;
                UPK2(x0, x1, dtp[i][jp]);
                float lr0 = (x0 > 0.0f) ? x0 : 0.2f * x0;
                float lr1 = (x1 > 0.0f) ? x1 : 0.2f * x1;
                lg += lr0 * sal[tc*8 + 2*jp] + lr1 * sal[tc*8 + 2*jp + 1];
            }
            const int d = edst[ge];
            const float a = __expf(lg + el_g[ge]);
            asm volatile("red.global.add.f32 [%0], %1;"
                         :: "l"(g_z + (size_t)d*8 + tc), "f"(a) : "memory");
            float* dstp = g_acc + (size_t)d*64 + tc*8;
            #pragma unroll
            for (int q = 0; q < 2; q++) {
                float4 v;
                UPK2(v.x, v.y, dtp[i][4 + 2*q]);
                UPK2(v.z, v.w, dtp[i][4 + 2*q + 1]);
                asm volatile("red.global.add.v4.f32 [%0], {%1,%2,%3,%4};"
                             :: "l"(dstp + q*4), "f"(v.x*a), "f"(v.y*a),
                                "f"(v.z*a), "f"(v.w*a) : "memory");
            }
        }
    }
}

// ---------------- final: 512 threads, 128-node tiles, 2n x 8c, fused FFN, dynamic tiles ----------------
#define FW_P   0
#define FW_1   4096
#define FW_2   16384
#define F_BP   28672
#define F_LNW  28736
#define F_LNB  28800
#define F_BF1  28864
#define F_BF2  29056
#define F_SS   29120
#define F_SQ   29248
#define F_XT   29376
#define F_YT   37824
#define SMEM_FIN 46272
#define NTF ((NDN + 127)/128)

__global__ void __launch_bounds__(512, 1)
k_final(const float* __restrict__ dst_f,
        const float* __restrict__ Wp, const float* __restrict__ bp,
        const float* __restrict__ lnw, const float* __restrict__ lnb,
        const float* __restrict__ Wf1, const float* __restrict__ bf1,
        const float* __restrict__ Wf2, const float* __restrict__ bf2,
        float* __restrict__ out) {
    extern __shared__ float sf[];
    __shared__ int s_tile;
    const int tid = threadIdx.x;
    for (int i = tid; i < 4096;  i += 512) sf[FW_P + i] = Wp[i];
    for (int i = tid; i < 12288; i += 512) sf[FW_1 + i] = Wf1[i];
    for (int i = tid; i < 12288; i += 512) sf[FW_2 + i] = Wf2[i];
    if (tid < 64) {
        sf[F_BP  + tid] = bp[tid];
        sf[F_LNW + tid] = lnw[tid];
        sf[F_LNB + tid] = lnb[tid];
        sf[F_BF2 + tid] = bf2[tid];
    }
    if (tid < 192) sf[F_BF1 + tid] = bf1[tid];

    const int lane = tid & 31, warp = tid >> 5;
    const int tc = warp & 7;
    const int n0 = ((warp >> 3) << 6) + lane*2;

    while (true) {
        if (tid == 0) s_tile = (int)atomicAdd(&g_ctrF, 1u);
        __syncthreads();   // covers weight staging on first iter; prior tile consumed
        const int tile = s_tile;
        if (tile >= NTF) break;
        const int base = tile * 128;
        if (tid < 128) { sf[F_SS + tid] = 0.0f; sf[F_SQ + tid] = 0.0f; }
        {
            const int n = tid >> 2, p = tid & 3;
            int gn = base + n; if (gn >= NDN) gn = NDN - 1;
            const float4* ar = (const float4*)(g_acc + (size_t)gn*64 + p*16);
            float z0 = g_z[(size_t)gn*8 + 2*p], z1 = g_z[(size_t)gn*8 + 2*p + 1];
            float r0 = (z0 > 0.0f) ? 1.0f/z0 : 0.0f;
            float r1 = (z1 > 0.0f) ? 1.0f/z1 : 0.0f;
            #pragma unroll
            for (int j = 0; j < 4; j++) {
                float4 v = ar[j];
                const float rr = (j < 2) ? r0 : r1;
                const int k0 = p*16 + j*4;
                sf[F_XT + (k0+0)*SDN + n] = v.x * rr;
                sf[F_XT + (k0+1)*SDN + n] = v.y * rr;
                sf[F_XT + (k0+2)*SDN + n] = v.z * rr;
                sf[F_XT + (k0+3)*SDN + n] = v.w * rr;
            }
        }
        __syncthreads();

        float emb[2][8];
        {
            u64 acc[2][4] = {};
            #pragma unroll 4
            for (int k = 0; k < 64; k++) {
                float2 xv = *(const float2*)(sf + F_XT + k*SDN + n0);
                ulonglong2 wa = *(const ulonglong2*)(sf + FW_P + k*64 + tc*8);
                ulonglong2 wb = *(const ulonglong2*)(sf + FW_P + k*64 + tc*8 + 4);
                u64 xp;
                PK2(xp, xv.x);
                FFMA2(acc[0][0], xp, wa.x, acc[0][0]); FFMA2(acc[0][1], xp, wa.y, acc[0][1]);
                FFMA2(acc[0][2], xp, wb.x, acc[0][2]); FFMA2(acc[0][3], xp, wb.y, acc[0][3]);
                PK2(xp, xv.y);
                FFMA2(acc[1][0], xp, wa.x, acc[1][0]); FFMA2(acc[1][1], xp, wa.y, acc[1][1]);
                FFMA2(acc[1][2], xp, wb.x, acc[1][2]); FFMA2(acc[1][3], xp, wb.y, acc[1][3]);
            }
            #pragma unroll
            for (int i = 0; i < 2; i++) {
                int gn = base + n0 + i; if (gn >= NDN) gn = NDN - 1;
                float4 d0 = *(const float4*)(dst_f + (size_t)gn*64 + tc*8);
                float4 d1 = *(const float4*)(dst_f + (size_t)gn*64 + tc*8 + 4);
                UPK2(emb[i][0], emb[i][1], acc[i][0]);
                UPK2(emb[i][2], emb[i][3], acc[i][1]);
                UPK2(emb[i][4], emb[i][5], acc[i][2]);
                UPK2(emb[i][6], emb[i][7], acc[i][3]);
                emb[i][0] += sf[F_BP + tc*8+0] + d0.x;
                emb[i][1] += sf[F_BP + tc*8+1] + d0.y;
                emb[i][2] += sf[F_BP + tc*8+2] + d0.z;
                emb[i][3] += sf[F_BP + tc*8+3] + d0.w;
                emb[i][4] += sf[F_BP + tc*8+4] + d1.x;
                emb[i][5] += sf[F_BP + tc*8+5] + d1.y;
                emb[i][6] += sf[F_BP + tc*8+6] + d1.z;
                emb[i][7] += sf[F_BP + tc*8+7] + d1.w;
            }
            #pragma unroll
            for (int i = 0; i < 2; i++) {
                float s = 0.f, q = 0.f;
                #pragma unroll
                for (int j = 0; j < 8; j++) { s += emb[i][j]; q += emb[i][j]*emb[i][j]; }
                atomicAdd(sf + F_SS + n0 + i, s);
                atomicAdd(sf + F_SQ + n0 + i, q);
            }
        }
        __syncthreads();

        {
            float mean[2], rs[2];
            #pragma unroll
            for (int i = 0; i < 2; i++) {
                mean[i] = sf[F_SS + n0 + i] * (1.0f/64.0f);
                float var = sf[F_SQ + n0 + i] * (1.0f/64.0f) - mean[i]*mean[i];
                rs[i] = rsqrtf(var + LNEPS);
            }
            #pragma unroll
            for (int j = 0; j < 8; j++) {
                const int c = tc*8 + j;
                const float lw = sf[F_LNW + c], lb = sf[F_LNB + c];
                float2 v;
                v.x = (emb[0][j] - mean[0]) * rs[0] * lw + lb;
                v.y = (emb[1][j] - mean[1]) * rs[1] * lw + lb;
                *(float2*)(sf + F_YT + c*SDN + n0) = v;
            }
        }
        __syncthreads();

        u64 oacc[2][4] = {};
        #pragma unroll
        for (int pp = 0; pp < 3; pp++) {
            {
                u64 acc[2][4] = {};
                #pragma unroll 4
                for (int k = 0; k < 64; k++) {
                    float2 xv = *(const float2*)(sf + F_YT + k*SDN + n0);
                    ulonglong2 wa = *(const ulonglong2*)(sf + FW_1 + k*192 + pp*64 + tc*8);
                    ulonglong2 wb = *(const ulonglong2*)(sf + FW_1 + k*192 + pp*64 + tc*8 + 4);
                    u64 xp;
                    PK2(xp, xv.x);
                    FFMA2(acc[0][0], xp, wa.x, acc[0][0]); FFMA2(acc[0][1], xp, wa.y, acc[0][1]);
                    FFMA2(acc[0][2], xp, wb.x, acc[0][2]); FFMA2(acc[0][3], xp, wb.y, acc[0][3]);
                    PK2(xp, xv.y);
                    FFMA2(acc[1][0], xp, wa.x, acc[1][0]); FFMA2(acc[1][1], xp, wa.y, acc[1][1]);
                    FFMA2(acc[1][2], xp, wb.x, acc[1][2]); FFMA2(acc[1][3], xp, wb.y, acc[1][3]);
                }
                float h[2][8];
                #pragma unroll
                for (int i = 0; i < 2; i++) {
                    UPK2(h[i][0], h[i][1], acc[i][0]);
                    UPK2(h[i][2], h[i][3], acc[i][1]);
                    UPK2(h[i][4], h[i][5], acc[i][2]);
                    UPK2(h[i][6], h[i][7], acc[i][3]);
                    #pragma unroll
                    for (int j = 0; j < 8; j++) {
                        float x = h[i][j] + sf[F_BF1 + pp*64 + tc*8 + j];
                        h[i][j] = x / (1.0f + __expf(-x));
                    }
                }
                #pragma unroll
                for (int j = 0; j < 8; j++) {
                    float2 v = make_float2(h[0][j], h[1][j]);
                    *(float2*)(sf + F_XT + (tc*8 + j)*SDN + n0) = v;
                }
            }
            __syncthreads();
            {
                #pragma unroll 4
                for (int k = 0; k < 64; k++) {
                    float2 xv = *(const float2*)(sf + F_XT + k*SDN + n0);
                    ulonglong2 wa = *(const ulonglong2*)(sf + FW_2 + (pp*64 + k)*64 + tc*8);
                    ulonglong2 wb = *(const ulonglong2*)(sf + FW_2 + (pp*64 + k)*64 + tc*8 + 4);
                    u64 xp;
                    PK2(xp, xv.x);
                    FFMA2(oacc[0][0], xp, wa.x, oacc[0][0]); FFMA2(oacc[0][1], xp, wa.y, oacc[0][1]);
                    FFMA2(oacc[0][2], xp, wb.x, oacc[0][2]); FFMA2(oacc[0][3], xp, wb.y, oacc[0][3]);
                    PK2(xp, xv.y);
                    FFMA2(oacc[1][0], xp, wa.x, oacc[1][0]); FFMA2(oacc[1][1], xp, wa.y, oacc[1][1]);
                    FFMA2(oacc[1][2], xp, wb.x, oacc[1][2]); FFMA2(oacc[1][3], xp, wb.y, oacc[1][3]);
                }
            }
            __syncthreads();
        }

        #pragma unroll
        for (int i = 0; i < 2; i++) {
            const int gn = base + n0 + i;
            if (gn >= NDN) continue;
            float o[8];
            UPK2(o[0], o[1], oacc[i][0]); UPK2(o[2], o[3], oacc[i][1]);
            UPK2(o[4], o[5], oacc[i][2]); UPK2(o[6], o[7], oacc[i][3]);
            float4 v0, v1;
            v0.x = o[0] + sf[F_BF2 + tc*8+0] + emb[i][0];
            v0.y = o[1] + sf[F_BF2 + tc*8+1] + emb[i][1];
            v0.z = o[2] + sf[F_BF2 + tc*8+2] + emb[i][2];
            v0.w = o[3] + sf[F_BF2 + tc*8+3] + emb[i][3];
            v1.x = o[4] + sf[F_BF2 + tc*8+4] + emb[i][4];
            v1.y = o[5] + sf[F_BF2 + tc*8+5] + emb[i][5];
            v1.z = o[6] + sf[F_BF2 + tc*8+6] + emb[i][6];
            v1.w = o[7] + sf[F_BF2 + tc*8+7] + emb[i][7];
            *(float4*)(out + (size_t)gn*64 + tc*8)     = v0;
            *(float4*)(out + (size_t)gn*64 + tc*8 + 4) = v1;
        }
    }
}

// ---------------- launch ----------------
extern "C" void kernel_launch(void* const* d_in, const int* in_sizes, int n_in,
                              void* d_out, int out_size) {
    const float* src_f        = (const float*)d_in[0];
    const float* dst_f        = (const float*)d_in[1];
    const float* edge_attr    = (const float*)d_in[2];
    const float* edge_scalars = (const float*)d_in[3];
    const float* edge_logits  = (const float*)d_in[4];
    const int*   edge_src     = (const int*)d_in[5];
    const int*   edge_dst     = (const int*)d_in[6];
    const float* ln_src_w = (const float*)d_in[7];
    const float* ln_src_b = (const float*)d_in[8];
    const float* W_src    = (const float*)d_in[9];
    const float* ln_dst_w = (const float*)d_in[10];
    const float* ln_dst_b = (const float*)d_in[11];
    const float* W_dst    = (const float*)d_in[12];
    const float* b_dst    = (const float*)d_in[13];
    const float* W_ea     = (const float*)d_in[14];
    const float* W_dtp    = (const float*)d_in[15];
    const float* W_r1     = (const float*)d_in[16];
    const float* b_r1     = (const float*)d_in[17];
    const float* W_r2     = (const float*)d_in[18];
    const float* b_r2     = (const float*)d_in[19];
    const float* alpha    = (const float*)d_in[20];
    const float* W_proj   = (const float*)d_in[21];
    const float* b_proj   = (const float*)d_in[22];
    const float* ln_post_w = (const float*)d_in[23];
    const float* ln_post_b = (const float*)d_in[24];
    const float* W_f1     = (const float*)d_in[25];
    const float* b_f1     = (const float*)d_in[26];
    const float* W_f2     = (const float*)d_in[27];
    const float* b_f2     = (const float*)d_in[28];
    float* out = (float*)d_out;

    cudaFuncSetAttribute(k_edge, cudaFuncAttributeMaxDynamicSharedMemorySize,
                         SMEM_EDGE_FLOATS * 4);
    cudaFuncSetAttribute(k_final, cudaFuncAttributeMaxDynamicSharedMemorySize,
                         SMEM_FIN * 4);
    cudaFuncSetAttribute(k_node, cudaFuncAttributeMaxDynamicSharedMemorySize,
                         KN_SMEM * 4);

    k_node<<<444, 512, KN_SMEM*4>>>(src_f, dst_f, ln_src_w, ln_src_b, W_src,
                                    ln_dst_w, ln_dst_b, W_dst, b_dst);
    k_edge<<<148, 256, SMEM_EDGE_FLOATS*4>>>(edge_scalars, edge_attr, edge_logits,
                                             edge_src, edge_dst,
                                             W_r1, b_r1, W_r2, b_r2, W_ea, W_dtp, alpha);
    k_final<<<148, 512, SMEM_FIN*4>>>(dst_f, W_proj, b_proj,
                                      ln_post_w, ln_post_b,
                                      W_f1, b_f1, W_f2, b_f2, out);
}

// round 16
// speedup vs baseline: 1.0706x; 1.0706x over previous
#include <cuda_runtime.h>
#include <cstdint>

#define NSN 50000
#define NDN 50000
#define EE  600000
#define CC  64
#define HH  8
#define LNEPS 1e-5f

typedef unsigned long long u64;

// packed f32x2 helpers (SASS FFMA2 — only reachable via PTX fma.rn.f32x2)
#define FFMA2(d, a, b, c) asm("fma.rn.f32x2 %0, %1, %2, %3;" : "=l"(d) : "l"(a), "l"(b), "l"(c))
#define MUL2(d, a, b)     asm("mul.rn.f32x2 %0, %1, %2;"     : "=l"(d) : "l"(a), "l"(b))
#define ADD2(d, a, b)     asm("add.rn.f32x2 %0, %1, %2;"     : "=l"(d) : "l"(a), "l"(b))
#define PK2(d, x)         asm("mov.b64 %0, {%1, %1};"        : "=l"(d) : "f"(x))
#define UPK2(lo, hi, v)   asm("mov.b64 {%0, %1}, %2;"        : "=f"(lo), "=f"(hi) : "l"(v))

// ---------------- scratch ----------------
__device__ float g_ms[(size_t)NSN*CC];
__device__ float g_md[(size_t)NDN*CC];
__device__ float g_z[(size_t)NDN*HH];
__device__ float g_acc[(size_t)NDN*CC];

// ---------------- node projections: 512 threads, 128-node tiles, 2n x 8c ----------------
// Also zeroes g_acc / g_z for dst tiles.
#define KN_SMEM 16960
#define SDN 132
__global__ void __launch_bounds__(512)
k_node(const float* __restrict__ src_f, const float* __restrict__ dst_f,
       const float* __restrict__ lnsw, const float* __restrict__ lnsb,
       const float* __restrict__ Wsrc,
       const float* __restrict__ lndw, const float* __restrict__ lndb,
       const float* __restrict__ Wdst, const float* __restrict__ bdst) {
    extern __shared__ float sn[];
    float* sW  = sn;
    float* sYt = sn + 8192;
    float* sBd = sn + 16640;
    float* sLn = sn + 16704;
    const int tid = threadIdx.x;
    for (int i = tid; i < 8192; i += 512) sW[i] = (i < 4096) ? Wsrc[i] : Wdst[i-4096];
    if (tid < 64) {
        sBd[tid] = bdst[tid];
        sLn[tid] = lnsw[tid]; sLn[64+tid] = lnsb[tid];
        sLn[128+tid] = lndw[tid]; sLn[192+tid] = lndb[tid];
    }
    const int NTS = (NSN + 127)/128, NTD = (NDN + 127)/128;
    const int lane = tid & 31, warp = tid >> 5;
    const int tc = warp & 7;
    const int n0 = ((warp >> 3) << 6) + lane*2;
    for (int tile = blockIdx.x; tile < NTS + NTD; tile += gridDim.x) {
        const bool isd = (tile >= NTS);
        const int base = (isd ? tile - NTS : tile) * 128;
        const int NV = isd ? NDN : NSN;
        __syncthreads();
        {
            const int n = tid >> 2, p = tid & 3;
            int gn = base + n; if (gn >= NV) gn = NV - 1;
            const float4* xr = (const float4*)((isd ? dst_f : src_f) + (size_t)gn*64 + p*16);
            float4 v[4]; float s = 0.f, q = 0.f;
            #pragma unroll
            for (int j = 0; j < 4; j++) {
                v[j] = xr[j];
                s += v[j].x + v[j].y + v[j].z + v[j].w;
                q += v[j].x*v[j].x + v[j].y*v[j].y + v[j].z*v[j].z + v[j].w*v[j].w;
            }
            s += __shfl_xor_sync(~0u, s, 1); s += __shfl_xor_sync(~0u, s, 2);
            q += __shfl_xor_sync(~0u, q, 1); q += __shfl_xor_sync(~0u, q, 2);
            const float mean = s * (1.0f/64.0f);
            const float var  = q * (1.0f/64.0f) - mean*mean;
            const float rs   = rsqrtf(var + LNEPS);
            const float* lw = sLn + (isd ? 128 : 0);
            const float* lb = sLn + (isd ? 192 : 64);
            #pragma unroll
            for (int j = 0; j < 4; j++) {
                const int k0 = p*16 + j*4;
                sYt[(k0+0)*SDN + n] = (v[j].x - mean)*rs*lw[k0+0] + lb[k0+0];
                sYt[(k0+1)*SDN + n] = (v[j].y - mean)*rs*lw[k0+1] + lb[k0+1];
                sYt[(k0+2)*SDN + n] = (v[j].z - mean)*rs*lw[k0+2] + lb[k0+2];
                sYt[(k0+3)*SDN + n] = (v[j].w - mean)*rs*lw[k0+3] + lb[k0+3];
            }
            if (isd && base + n < NDN) {
                float4 z = make_float4(0.f, 0.f, 0.f, 0.f);
                *(float4*)(g_acc + (size_t)(base + n)*64 + p*16)      = z;
                *(float4*)(g_acc + (size_t)(base + n)*64 + p*16 + 4)  = z;
                *(float4*)(g_acc + (size_t)(base + n)*64 + p*16 + 8)  = z;
                *(float4*)(g_acc + (size_t)(base + n)*64 + p*16 + 12) = z;
                *(float2*)(g_z + (size_t)(base + n)*8 + p*2) = make_float2(0.f, 0.f);
            }
        }
        __syncthreads();
        {
            const float* W = sW + (isd ? 4096 : 0);
            u64 acc[2][4] = {};
            #pragma unroll 4
            for (int k = 0; k < 64; k++) {
                float2 xv = *(const float2*)(sYt + k*SDN + n0);
                ulonglong2 wa = *(const ulonglong2*)(W + k*64 + tc*8);
                ulonglong2 wb = *(const ulonglong2*)(W + k*64 + tc*8 + 4);
                u64 xp;
                PK2(xp, xv.x);
                FFMA2(acc[0][0], xp, wa.x, acc[0][0]); FFMA2(acc[0][1], xp, wa.y, acc[0][1]);
                FFMA2(acc[0][2], xp, wb.x, acc[0][2]); FFMA2(acc[0][3], xp, wb.y, acc[0][3]);
                PK2(xp, xv.y);
                FFMA2(acc[1][0], xp, wa.x, acc[1][0]); FFMA2(acc[1][1], xp, wa.y, acc[1][1]);
                FFMA2(acc[1][2], xp, wb.x, acc[1][2]); FFMA2(acc[1][3], xp, wb.y, acc[1][3]);
            }
            float* outp = isd ? g_md : g_ms;
            #pragma unroll
            for (int i = 0; i < 2; i++) {
                const int gn = base + n0 + i;
                if (gn >= NV) continue;
                float4 o0, o1;
                UPK2(o0.x, o0.y, acc[i][0]); UPK2(o0.z, o0.w, acc[i][1]);
                UPK2(o1.x, o1.y, acc[i][2]); UPK2(o1.z, o1.w, acc[i][3]);
                if (isd) {
                    o0.x += sBd[tc*8+0]; o0.y += sBd[tc*8+1];
                    o0.z += sBd[tc*8+2]; o0.w += sBd[tc*8+3];
                    o1.x += sBd[tc*8+4]; o1.y += sBd[tc*8+5];
                    o1.z += sBd[tc*8+6]; o1.w += sBd[tc*8+7];
                }
                *(float4*)(outp + (size_t)gn*64 + tc*8)     = o0;
                *(float4*)(outp + (size_t)gn*64 + tc*8 + 4) = o1;
            }
        }
    }
}

// ---------------- heavy fused edge kernel: 256 threads, 4e x 16c strips, ES/EA prefetch ----------------
#define TEDGE 128
#define NTILE2 ((EE + TEDGE - 1) / TEDGE)
#define SDE 132
#define OFF_WR1   0
#define OFF_WR2   4096
#define OFF_WEA   12288
#define OFF_WDTP  13312
#define OFF_BR1   21504
#define OFF_BR2   21568
#define OFF_AL    21696
#define OFF_ESt   21760
#define OFF_Rt    (OFF_ESt + 8448)
#define OFF_MSGt  (OFF_Rt  + 8448)
#define OFF_EAt   (OFF_MSGt+ 8448)
#define SMEM_EDGE_FLOATS (OFF_EAt + 2112)

__global__ void __launch_bounds__(256, 1)
k_edge(const float* __restrict__ es_g, const float* __restrict__ ea_g,
       const float* __restrict__ el_g,
       const int* __restrict__ esrc, const int* __restrict__ edst,
       const float* __restrict__ Wr1, const float* __restrict__ br1,
       const float* __restrict__ Wr2, const float* __restrict__ br2,
       const float* __restrict__ Wea, const float* __restrict__ Wdtp,
       const float* __restrict__ alpha) {
    extern __shared__ float sm[];
    float* sWr1  = sm + OFF_WR1;
    float* sWr2  = sm + OFF_WR2;
    float* sWea  = sm + OFF_WEA;
    float* sWdtp = sm + OFF_WDTP;
    float* sbr1  = sm + OFF_BR1;
    float* sbr2  = sm + OFF_BR2;
    float* sal   = sm + OFF_AL;
    float* sESt  = sm + OFF_ESt;
    float* sRt   = sm + OFF_Rt;
    float* sMSGt = sm + OFF_MSGt;
    float* sEAt  = sm + OFF_EAt;

    const int tid = threadIdx.x;
    for (int i = tid; i < 4096; i += 256) sWr1[i]  = Wr1[i];
    for (int i = tid; i < 8192; i += 256) sWr2[i]  = Wr2[i];
    for (int i = tid; i < 1024; i += 256) sWea[i]  = Wea[i];
    for (int i = tid; i < 8192; i += 256) sWdtp[i] = Wdtp[i];
    if (tid < 64)  sbr1[tid] = br1[tid];
    if (tid < 128) sbr2[tid] = br2[tid];
    if (tid < 64)  sal[tid]  = alpha[tid];

    const int te = tid & 31;
    const int tc = tid >> 5;     // warp = head; logit strip [tc*8,+8), val strip [64+tc*8,+8)
    const int e0 = te * 4;

    const int e_st = tid >> 2, p_st = tid & 3;   // staging item (j=0); j=1 is e_st+64

    // cross-tile register prefetch of ES (streamed, DRAM-latency) and EA
    float4 pes[2][4];
    float4 pea[2];
#define PREFETCH_ES(t) do {                                                   \
        const int bb = (t) * TEDGE;                                           \
        int geA = bb + e_st;      if (geA >= EE) geA = EE - 1;                \
        int geB = bb + e_st + 64; if (geB >= EE) geB = EE - 1;                \
        const float4* rA = (const float4*)(es_g + (size_t)geA*64 + p_st*16);  \
        const float4* rB = (const float4*)(es_g + (size_t)geB*64 + p_st*16);  \
        pes[0][0]=rA[0]; pes[0][1]=rA[1]; pes[0][2]=rA[2]; pes[0][3]=rA[3];   \
        pes[1][0]=rB[0]; pes[1][1]=rB[1]; pes[1][2]=rB[2]; pes[1][3]=rB[3];   \
        int geC = bb + e_st;      if (geC >= EE) geC = EE - 1;                \
        int geD = bb + e_st + 64; if (geD >= EE) geD = EE - 1;                \
        pea[0] = *(const float4*)(ea_g + (size_t)geC*16 + p_st*4);            \
        pea[1] = *(const float4*)(ea_g + (size_t)geD*16 + p_st*4);            \
    } while (0)

    PREFETCH_ES(blockIdx.x);

    for (int tile = blockIdx.x; tile < NTILE2; tile += gridDim.x) {
        const int base = tile * TEDGE;
        __syncthreads();   // previous tile fully consumed

        // ---- staging ----
        {
            // issue gather loads first (L2-resident tables)
            float4 gms[2][4], gmd[2][4];
            #pragma unroll
            for (int j = 0; j < 2; j++) {
                const int e = e_st + j*64;
                int ge = base + e; if (ge >= EE) ge = EE - 1;
                const int sidx = esrc[ge], didx = edst[ge];
                const float4* msr = (const float4*)(g_ms + (size_t)sidx*64 + p_st*16);
                const float4* mdr = (const float4*)(g_md + (size_t)didx*64 + p_st*16);
                #pragma unroll
                for (int q = 0; q < 4; q++) { gms[j][q] = msr[q]; gmd[j][q] = mdr[q]; }
            }
            // ES / EA stores from prefetched registers (no latency)
            #pragma unroll
            for (int j = 0; j < 2; j++) {
                const int e = e_st + j*64;
                #pragma unroll
                for (int q = 0; q < 4; q++) {
                    const int k0 = p_st*16 + q*4;
                    sESt[(k0+0)*SDE + e] = pes[j][q].x;
                    sESt[(k0+1)*SDE + e] = pes[j][q].y;
                    sESt[(k0+2)*SDE + e] = pes[j][q].z;
                    sESt[(k0+3)*SDE + e] = pes[j][q].w;
                }
                const int ka = p_st*4;
                sEAt[(ka+0)*SDE + e] = pea[j].x;
                sEAt[(ka+1)*SDE + e] = pea[j].y;
                sEAt[(ka+2)*SDE + e] = pea[j].z;
                sEAt[(ka+3)*SDE + e] = pea[j].w;
            }
            // MSG = ms + md, transposed stores
            #pragma unroll
            for (int j = 0; j < 2; j++) {
                const int e = e_st + j*64;
                #pragma unroll
                for (int q = 0; q < 4; q++) {
                    const int k0 = p_st*16 + q*4;
                    sMSGt[(k0+0)*SDE + e] = gms[j][q].x + gmd[j][q].x;
                    sMSGt[(k0+1)*SDE + e] = gms[j][q].y + gmd[j][q].y;
                    sMSGt[(k0+2)*SDE + e] = gms[j][q].z + gmd[j][q].z;
                    sMSGt[(k0+3)*SDE + e] = gms[j][q].w + gmd[j][q].w;
                }
            }
        }
        // kick off next tile's ES/EA loads; latency hides under the GEMM phases
        {
            int nt = tile + gridDim.x; if (nt >= NTILE2) nt = NTILE2 - 1;
            PREFETCH_ES(nt);
        }
        __syncthreads();

        // ---- GEMM1 + Gea + T (cols tc*8..+8 of 64) ----
        u64 ea2[4][4] = {};
        {
            u64 acc[4][4] = {};
            #pragma unroll 4
            for (int k = 0; k < 64; k++) {
                float4 xv = *(const float4*)(sESt + k*SDE + e0);
                ulonglong2 wa = *(const ulonglong2*)(sWr1 + k*64 + tc*8);
                ulonglong2 wb = *(const ulonglong2*)(sWr1 + k*64 + tc*8 + 4);
                u64 xp;
                PK2(xp, xv.x);
                FFMA2(acc[0][0], xp, wa.x, acc[0][0]); FFMA2(acc[0][1], xp, wa.y, acc[0][1]);
                FFMA2(acc[0][2], xp, wb.x, acc[0][2]); FFMA2(acc[0][3], xp, wb.y, acc[0][3]);
                PK2(xp, xv.y);
                FFMA2(acc[1][0], xp, wa.x, acc[1][0]); FFMA2(acc[1][1], xp, wa.y, acc[1][1]);
                FFMA2(acc[1][2], xp, wb.x, acc[1][2]); FFMA2(acc[1][3], xp, wb.y, acc[1][3]);
                PK2(xp, xv.z);
                FFMA2(acc[2][0], xp, wa.x, acc[2][0]); FFMA2(acc[2][1], xp, wa.y, acc[2][1]);
                FFMA2(acc[2][2], xp, wb.x, acc[2][2]); FFMA2(acc[2][3], xp, wb.y, acc[2][3]);
                PK2(xp, xv.w);
                FFMA2(acc[3][0], xp, wa.x, acc[3][0]); FFMA2(acc[3][1], xp, wa.y, acc[3][1]);
                FFMA2(acc[3][2], xp, wb.x, acc[3][2]); FFMA2(acc[3][3], xp, wb.y, acc[3][3]);
            }
            #pragma unroll
            for (int jp = 0; jp < 4; jp++) {
                float lo[4], hi[4];
                #pragma unroll
                for (int i = 0; i < 4; i++) UPK2(lo[i], hi[i], acc[i][jp]);
                float b0 = sbr1[tc*8 + 2*jp], b1 = sbr1[tc*8 + 2*jp + 1];
                float4 v0, v1;
                v0.x = lo[0]+b0; v0.y = lo[1]+b0; v0.z = lo[2]+b0; v0.w = lo[3]+b0;
                v1.x = hi[0]+b1; v1.y = hi[1]+b1; v1.z = hi[2]+b1; v1.w = hi[3]+b1;
                v0.x /= (1.0f + __expf(-v0.x)); v0.y /= (1.0f + __expf(-v0.y));
                v0.z /= (1.0f + __expf(-v0.z)); v0.w /= (1.0f + __expf(-v0.w));
                v1.x /= (1.0f + __expf(-v1.x)); v1.y /= (1.0f + __expf(-v1.y));
                v1.z /= (1.0f + __expf(-v1.z)); v1.w /= (1.0f + __expf(-v1.w));
                *(float4*)(sRt + (tc*8 + 2*jp)*SDE   + e0) = v0;
                *(float4*)(sRt + (tc*8 + 2*jp+1)*SDE + e0) = v1;
            }
            #pragma unroll
            for (int k = 0; k < 16; k++) {
                float4 xv = *(const float4*)(sEAt + k*SDE + e0);
                ulonglong2 wa = *(const ulonglong2*)(sWea + k*64 + tc*8);
                ulonglong2 wb = *(const ulonglong2*)(sWea + k*64 + tc*8 + 4);
                u64 xp;
                PK2(xp, xv.x);
                FFMA2(ea2[0][0], xp, wa.x, ea2[0][0]); FFMA2(ea2[0][1], xp, wa.y, ea2[0][1]);
                FFMA2(ea2[0][2], xp, wb.x, ea2[0][2]); FFMA2(ea2[0][3], xp, wb.y, ea2[0][3]);
                PK2(xp, xv.y);
                FFMA2(ea2[1][0], xp, wa.x, ea2[1][0]); FFMA2(ea2[1][1], xp, wa.y, ea2[1][1]);
                FFMA2(ea2[1][2], xp, wb.x, ea2[1][2]); FFMA2(ea2[1][3], xp, wb.y, ea2[1][3]);
                PK2(xp, xv.z);
                FFMA2(ea2[2][0], xp, wa.x, ea2[2][0]); FFMA2(ea2[2][1], xp, wa.y, ea2[2][1]);
                FFMA2(ea2[2][2], xp, wb.x, ea2[2][2]); FFMA2(ea2[2][3], xp, wb.y, ea2[2][3]);
                PK2(xp, xv.w);
                FFMA2(ea2[3][0], xp, wa.x, ea2[3][0]); FFMA2(ea2[3][1], xp, wa.y, ea2[3][1]);
                FFMA2(ea2[3][2], xp, wb.x, ea2[3][2]); FFMA2(ea2[3][3], xp, wb.y, ea2[3][3]);
            }
            #pragma unroll
            for (int jp = 0; jp < 4; jp++) {
                #pragma unroll
                for (int h = 0; h < 2; h++) {
                    const int c = tc*8 + 2*jp + h;
                    float4 m4 = *(float4*)(sMSGt + c*SDE + e0);
                    float v0, v1, v2, v3, dummy;
                    if (h == 0) {
                        UPK2(v0, dummy, ea2[0][jp]); UPK2(v1, dummy, ea2[1][jp]);
                        UPK2(v2, dummy, ea2[2][jp]); UPK2(v3, dummy, ea2[3][jp]);
                    } else {
                        UPK2(dummy, v0, ea2[0][jp]); UPK2(dummy, v1, ea2[1][jp]);
                        UPK2(dummy, v2, ea2[2][jp]); UPK2(dummy, v3, ea2[3][jp]);
                    }
                    m4.x *= v0; m4.y *= v1; m4.z *= v2; m4.w *= v3;
                    *(float4*)(sMSGt + c*SDE + e0) = m4;
                }
            }
        }
        __syncthreads();

        // ---- GEMM2: w_edge, strips [tc*8,+8) and [64+tc*8,+8) ----
        u64 we[4][8];
        {
            u64 acc[4][8] = {};
            #pragma unroll 2
            for (int k = 0; k < 64; k++) {
                float4 xv = *(const float4*)(sRt + k*SDE + e0);
                const float* wrow = sWr2 + k*128;
                ulonglong2 wa = *(const ulonglong2*)(wrow + tc*8);
                ulonglong2 wb = *(const ulonglong2*)(wrow + tc*8 + 4);
                ulonglong2 wc = *(const ulonglong2*)(wrow + 64 + tc*8);
                ulonglong2 wd = *(const ulonglong2*)(wrow + 64 + tc*8 + 4);
                u64 xp;
                #pragma unroll
                for (int i = 0; i < 4; i++) {
                    float x = (i==0) ? xv.x : (i==1) ? xv.y : (i==2) ? xv.z : xv.w;
                    PK2(xp, x);
                    FFMA2(acc[i][0], xp, wa.x, acc[i][0]); FFMA2(acc[i][1], xp, wa.y, acc[i][1]);
                    FFMA2(acc[i][2], xp, wb.x, acc[i][2]); FFMA2(acc[i][3], xp, wb.y, acc[i][3]);
                    FFMA2(acc[i][4], xp, wc.x, acc[i][4]); FFMA2(acc[i][5], xp, wc.y, acc[i][5]);
                    FFMA2(acc[i][6], xp, wd.x, acc[i][6]); FFMA2(acc[i][7], xp, wd.y, acc[i][7]);
                }
            }
            #pragma unroll
            for (int i = 0; i < 4; i++) {
                #pragma unroll
                for (int jp = 0; jp < 4; jp++) {
                    u64 bA = *(const u64*)(sbr2 + tc*8 + 2*jp);
                    u64 bB = *(const u64*)(sbr2 + 64 + tc*8 + 2*jp);
                    ADD2(we[i][jp],   acc[i][jp],   bA);
                    ADD2(we[i][jp+4], acc[i][jp+4], bB);
                }
            }
        }

        // ---- GEMM3: dtp, same strips ----
        u64 dtp[4][8];
        {
            u64 acc[4][8] = {};
            #pragma unroll 2
            for (int k = 0; k < 64; k++) {
                float4 xv = *(const float4*)(sMSGt + k*SDE + e0);
                const float* wrow = sWdtp + k*128;
                ulonglong2 wa = *(const ulonglong2*)(wrow + tc*8);
                ulonglong2 wb = *(const ulonglong2*)(wrow + tc*8 + 4);
                ulonglong2 wc = *(const ulonglong2*)(wrow + 64 + tc*8);
                ulonglong2 wd = *(const ulonglong2*)(wrow + 64 + tc*8 + 4);
                u64 xp;
                #pragma unroll
                for (int i = 0; i < 4; i++) {
                    float x = (i==0) ? xv.x : (i==1) ? xv.y : (i==2) ? xv.z : xv.w;
                    PK2(xp, x);
                    FFMA2(acc[i][0], xp, wa.x, acc[i][0]); FFMA2(acc[i][1], xp, wa.y, acc[i][1]);
                    FFMA2(acc[i][2], xp, wb.x, acc[i][2]); FFMA2(acc[i][3], xp, wb.y, acc[i][3]);
                    FFMA2(acc[i][4], xp, wc.x, acc[i][4]); FFMA2(acc[i][5], xp, wc.y, acc[i][5]);
                    FFMA2(acc[i][6], xp, wd.x, acc[i][6]); FFMA2(acc[i][7], xp, wd.y, acc[i][7]);
                }
            }
            #pragma unroll
            for (int i = 0; i < 4; i++)
                #pragma unroll
                for (int jp = 0; jp < 8; jp++)
                    MUL2(dtp[i][jp], acc[i][jp], we[i][jp]);
        }

        // ---- fused epilogue: warp owns head tc end-to-end ----
        #pragma unroll
        for (int i = 0; i < 4; i++) {
            const int ge = base + e0 + i;
            if (ge >= EE) continue;
            float lg = 0.0f;
            #pragma unroll
            for (int jp = 0; jp < 4; jp++) {
                float x0, x1;
                UPK2(x0, x1, dtp[i][jp]);
                float lr0 = (x0 > 0.0f) ? x0 : 0.2f * x0;
                float lr1 = (x1 > 0.0f) ? x1 : 0.2f * x1;
                lg += lr0 * sal[tc*8 + 2*jp] + lr1 * sal[tc*8 + 2*jp + 1];
            }
            const int d = edst[ge];
            const float a = __expf(lg + el_g[ge]);
            asm volatile("red.global.add.f32 [%0], %1;"
                         :: "l"(g_z + (size_t)d*8 + tc), "f"(a) : "memory");
            float* dstp = g_acc + (size_t)d*64 + tc*8;
            #pragma unroll
            for (int q = 0; q < 2; q++) {
                float4 v;
                UPK2(v.x, v.y, dtp[i][4 + 2*q]);
                UPK2(v.z, v.w, dtp[i][4 + 2*q + 1]);
                asm volatile("red.global.add.v4.f32 [%0], {%1,%2,%3,%4};"
                             :: "l"(dstp + q*4), "f"(v.x*a), "f"(v.y*a),
                                "f"(v.z*a), "f"(v.w*a) : "memory");
            }
        }
    }
}

// ---------------- final: 512 threads, 128-node tiles, 2n x 8c, fused FFN ----------------
#define FW_P   0
#define FW_1   4096
#define FW_2   16384
#define F_BP   28672
#define F_LNW  28736
#define F_LNB  28800
#define F_BF1  28864
#define F_BF2  29056
#define F_SS   29120
#define F_SQ   29248
#define F_XT   29376
#define F_YT   37824
#define SMEM_FIN 46272

__global__ void __launch_bounds__(512, 1)
k_final(const float* __restrict__ dst_f,
        const float* __restrict__ Wp, const float* __restrict__ bp,
        const float* __restrict__ lnw, const float* __restrict__ lnb,
        const float* __restrict__ Wf1, const float* __restrict__ bf1,
        const float* __restrict__ Wf2, const float* __restrict__ bf2,
        float* __restrict__ out) {
    extern __shared__ float sf[];
    const int tid = threadIdx.x;
    for (int i = tid; i < 4096;  i += 512) sf[FW_P + i] = Wp[i];
    for (int i = tid; i < 12288; i += 512) sf[FW_1 + i] = Wf1[i];
    for (int i = tid; i < 12288; i += 512) sf[FW_2 + i] = Wf2[i];
    if (tid < 64) {
        sf[F_BP  + tid] = bp[tid];
        sf[F_LNW + tid] = lnw[tid];
        sf[F_LNB + tid] = lnb[tid];
        sf[F_BF2 + tid] = bf2[tid];
    }
    if (tid < 192) sf[F_BF1 + tid] = bf1[tid];

    const int NT = (NDN + 127)/128;
    const int lane = tid & 31, warp = tid >> 5;
    const int tc = warp & 7;
    const int n0 = ((warp >> 3) << 6) + lane*2;

    for (int tile = blockIdx.x; tile < NT; tile += gridDim.x) {
        const int base = tile * 128;
        __syncthreads();
        if (tid < 128) { sf[F_SS + tid] = 0.0f; sf[F_SQ + tid] = 0.0f; }
        {
            const int n = tid >> 2, p = tid & 3;
            int gn = base + n; if (gn >= NDN) gn = NDN - 1;
            const float4* ar = (const float4*)(g_acc + (size_t)gn*64 + p*16);
            float z0 = g_z[(size_t)gn*8 + 2*p], z1 = g_z[(size_t)gn*8 + 2*p + 1];
            float r0 = (z0 > 0.0f) ? 1.0f/z0 : 0.0f;
            float r1 = (z1 > 0.0f) ? 1.0f/z1 : 0.0f;
            #pragma unroll
            for (int j = 0; j < 4; j++) {
                float4 v = ar[j];
                const float rr = (j < 2) ? r0 : r1;
                const int k0 = p*16 + j*4;
                sf[F_XT + (k0+0)*SDN + n] = v.x * rr;
                sf[F_XT + (k0+1)*SDN + n] = v.y * rr;
                sf[F_XT + (k0+2)*SDN + n] = v.z * rr;
                sf[F_XT + (k0+3)*SDN + n] = v.w * rr;
            }
        }
        __syncthreads();

        float emb[2][8];
        {
            u64 acc[2][4] = {};
            #pragma unroll 4
            for (int k = 0; k < 64; k++) {
                float2 xv = *(const float2*)(sf + F_XT + k*SDN + n0);
                ulonglong2 wa = *(const ulonglong2*)(sf + FW_P + k*64 + tc*8);
                ulonglong2 wb = *(const ulonglong2*)(sf + FW_P + k*64 + tc*8 + 4);
                u64 xp;
                PK2(xp, xv.x);
                FFMA2(acc[0][0], xp, wa.x, acc[0][0]); FFMA2(acc[0][1], xp, wa.y, acc[0][1]);
                FFMA2(acc[0][2], xp, wb.x, acc[0][2]); FFMA2(acc[0][3], xp, wb.y, acc[0][3]);
                PK2(xp, xv.y);
                FFMA2(acc[1][0], xp, wa.x, acc[1][0]); FFMA2(acc[1][1], xp, wa.y, acc[1][1]);
                FFMA2(acc[1][2], xp, wb.x, acc[1][2]); FFMA2(acc[1][3], xp, wb.y, acc[1][3]);
            }
            #pragma unroll
            for (int i = 0; i < 2; i++) {
                int gn = base + n0 + i; if (gn >= NDN) gn = NDN - 1;
                float4 d0 = *(const float4*)(dst_f + (size_t)gn*64 + tc*8);
                float4 d1 = *(const float4*)(dst_f + (size_t)gn*64 + tc*8 + 4);
                UPK2(emb[i][0], emb[i][1], acc[i][0]);
                UPK2(emb[i][2], emb[i][3], acc[i][1]);
                UPK2(emb[i][4], emb[i][5], acc[i][2]);
                UPK2(emb[i][6], emb[i][7], acc[i][3]);
                emb[i][0] += sf[F_BP + tc*8+0] + d0.x;
                emb[i][1] += sf[F_BP + tc*8+1] + d0.y;
                emb[i][2] += sf[F_BP + tc*8+2] + d0.z;
                emb[i][3] += sf[F_BP + tc*8+3] + d0.w;
                emb[i][4] += sf[F_BP + tc*8+4] + d1.x;
                emb[i][5] += sf[F_BP + tc*8+5] + d1.y;
                emb[i][6] += sf[F_BP + tc*8+6] + d1.z;
                emb[i][7] += sf[F_BP + tc*8+7] + d1.w;
            }
            #pragma unroll
            for (int i = 0; i < 2; i++) {
                float s = 0.f, q = 0.f;
                #pragma unroll
                for (int j = 0; j < 8; j++) { s += emb[i][j]; q += emb[i][j]*emb[i][j]; }
                atomicAdd(sf + F_SS + n0 + i, s);
                atomicAdd(sf + F_SQ + n0 + i, q);
            }
        }
        __syncthreads();

        {
            float mean[2], rs[2];
            #pragma unroll
            for (int i = 0; i < 2; i++) {
                mean[i] = sf[F_SS + n0 + i] * (1.0f/64.0f);
                float var = sf[F_SQ + n0 + i] * (1.0f/64.0f) - mean[i]*mean[i];
                rs[i] = rsqrtf(var + LNEPS);
            }
            #pragma unroll
            for (int j = 0; j < 8; j++) {
                const int c = tc*8 + j;
                const float lw = sf[F_LNW + c], lb = sf[F_LNB + c];
                float2 v;
                v.x = (emb[0][j] - mean[0]) * rs[0] * lw + lb;
                v.y = (emb[1][j] - mean[1]) * rs[1] * lw + lb;
                *(float2*)(sf + F_YT + c*SDN + n0) = v;
            }
        }
        __syncthreads();

        u64 oacc[2][4] = {};
        #pragma unroll
        for (int pp = 0; pp < 3; pp++) {
            {
                u64 acc[2][4] = {};
                #pragma unroll 4
                for (int k = 0; k < 64; k++) {
                    float2 xv = *(const float2*)(sf + F_YT + k*SDN + n0);
                    ulonglong2 wa = *(const ulonglong2*)(sf + FW_1 + k*192 + pp*64 + tc*8);
                    ulonglong2 wb = *(const ulonglong2*)(sf + FW_1 + k*192 + pp*64 + tc*8 + 4);
                    u64 xp;
                    PK2(xp, xv.x);
                    FFMA2(acc[0][0], xp, wa.x, acc[0][0]); FFMA2(acc[0][1], xp, wa.y, acc[0][1]);
                    FFMA2(acc[0][2], xp, wb.x, acc[0][2]); FFMA2(acc[0][3], xp, wb.y, acc[0][3]);
                    PK2(xp, xv.y);
                    FFMA2(acc[1][0], xp, wa.x, acc[1][0]); FFMA2(acc[1][1], xp, wa.y, acc[1][1]);
                    FFMA2(acc[1][2], xp, wb.x, acc[1][2]); FFMA2(acc[1][3], xp, wb.y, acc[1][3]);
                }
                float h[2][8];
                #pragma unroll
                for (int i = 0; i < 2; i++) {
                    UPK2(h[i][0], h[i][1], acc[i][0]);
                    UPK2(h[i][2], h[i][3], acc[i][1]);
                    UPK2(h[i][4], h[i][5], acc[i][2]);
                    UPK2(h[i][6], h[i][7], acc[i][3]);
                    #pragma unroll
                    for (int j = 0; j < 8; j++) {
                        float x = h[i][j] + sf[F_BF1 + pp*64 + tc*8 + j];
                        h[i][j] = x / (1.0f + __expf(-x));
                    }
                }
                #pragma unroll
                for (int j = 0; j < 8; j++) {
                    float2 v = make_float2(h[0][j], h[1][j]);
                    *(float2*)(sf + F_XT + (tc*8 + j)*SDN + n0) = v;
                }
            }
            __syncthreads();
            {
                #pragma unroll 4
                for (int k = 0; k < 64; k++) {
                    float2 xv = *(const float2*)(sf + F_XT + k*SDN + n0);
                    ulonglong2 wa = *(const ulonglong2*)(sf + FW_2 + (pp*64 + k)*64 + tc*8);
                    ulonglong2 wb = *(const ulonglong2*)(sf + FW_2 + (pp*64 + k)*64 + tc*8 + 4);
                    u64 xp;
                    PK2(xp, xv.x);
                    FFMA2(oacc[0][0], xp, wa.x, oacc[0][0]); FFMA2(oacc[0][1], xp, wa.y, oacc[0][1]);
                    FFMA2(oacc[0][2], xp, wb.x, oacc[0][2]); FFMA2(oacc[0][3], xp, wb.y, oacc[0][3]);
                    PK2(xp, xv.y);
                    FFMA2(oacc[1][0], xp, wa.x, oacc[1][0]); FFMA2(oacc[1][1], xp, wa.y, oacc[1][1]);
                    FFMA2(oacc[1][2], xp, wb.x, oacc[1][2]); FFMA2(oacc[1][3], xp, wb.y, oacc[1][3]);
                }
            }
            if (pp < 2) __syncthreads();
        }

        #pragma unroll
        for (int i = 0; i < 2; i++) {
            const int gn = base + n0 + i;
            if (gn >= NDN) continue;
            float o[8];
            UPK2(o[0], o[1], oacc[i][0]); UPK2(o[2], o[3], oacc[i][1]);
            UPK2(o[4], o[5], oacc[i][2]); UPK2(o[6], o[7], oacc[i][3]);
            float4 v0, v1;
            v0.x = o[0] + sf[F_BF2 + tc*8+0] + emb[i][0];
            v0.y = o[1] + sf[F_BF2 + tc*8+1] + emb[i][1];
            v0.z = o[2] + sf[F_BF2 + tc*8+2] + emb[i][2];
            v0.w = o[3] + sf[F_BF2 + tc*8+3] + emb[i][3];
            v1.x = o[4] + sf[F_BF2 + tc*8+4] + emb[i][4];
            v1.y = o[5] + sf[F_BF2 + tc*8+5] + emb[i][5];
            v1.z = o[6] + sf[F_BF2 + tc*8+6] + emb[i][6];
            v1.w = o[7] + sf[F_BF2 + tc*8+7] + emb[i][7];
            *(float4*)(out + (size_t)gn*64 + tc*8)     = v0;
            *(float4*)(out + (size_t)gn*64 + tc*8 + 4) = v1;
        }
    }
}

// ---------------- launch ----------------
extern "C" void kernel_launch(void* const* d_in, const int* in_sizes, int n_in,
                              void* d_out, int out_size) {
    const float* src_f        = (const float*)d_in[0];
    const float* dst_f        = (const float*)d_in[1];
    const float* edge_attr    = (const float*)d_in[2];
    const float* edge_scalars = (const float*)d_in[3];
    const float* edge_logits  = (const float*)d_in[4];
    const int*   edge_src     = (const int*)d_in[5];
    const int*   edge_dst     = (const int*)d_in[6];
    const float* ln_src_w = (const float*)d_in[7];
    const float* ln_src_b = (const float*)d_in[8];
    const float* W_src    = (const float*)d_in[9];
    const float* ln_dst_w = (const float*)d_in[10];
    const float* ln_dst_b = (const float*)d_in[11];
    const float* W_dst    = (const float*)d_in[12];
    const float* b_dst    = (const float*)d_in[13];
    const float* W_ea     = (const float*)d_in[14];
    const float* W_dtp    = (const float*)d_in[15];
    const float* W_r1     = (const float*)d_in[16];
    const float* b_r1     = (const float*)d_in[17];
    const float* W_r2     = (const float*)d_in[18];
    const float* b_r2     = (const float*)d_in[19];
    const float* alpha    = (const float*)d_in[20];
    const float* W_proj   = (const float*)d_in[21];
    const float* b_proj   = (const float*)d_in[22];
    const float* ln_post_w = (const float*)d_in[23];
    const float* ln_post_b = (const float*)d_in[24];
    const float* W_f1     = (const float*)d_in[25];
    const float* b_f1     = (const float*)d_in[26];
    const float* W_f2     = (const float*)d_in[27];
    const float* b_f2     = (const float*)d_in[28];
    float* out = (float*)d_out;

    cudaFuncSetAttribute(k_edge, cudaFuncAttributeMaxDynamicSharedMemorySize,
                         SMEM_EDGE_FLOATS * 4);
    cudaFuncSetAttribute(k_final, cudaFuncAttributeMaxDynamicSharedMemorySize,
                         SMEM_FIN * 4);
    cudaFuncSetAttribute(k_node, cudaFuncAttributeMaxDynamicSharedMemorySize,
                         KN_SMEM * 4);

    k_node<<<296, 512, KN_SMEM*4>>>(src_f, dst_f, ln_src_w, ln_src_b, W_src,
                                    ln_dst_w, ln_dst_b, W_dst, b_dst);
    k_edge<<<296, 256, SMEM_EDGE_FLOATS*4>>>(edge_scalars, edge_attr, edge_logits,
                                             edge_src, edge_dst,
                                             W_r1, b_r1, W_r2, b_r2, W_ea, W_dtp, alpha);
    k_final<<<148, 512, SMEM_FIN*4>>>(dst_f, W_proj, b_proj,
                                      ln_post_w, ln_post_b,
                                      W_f1, b_f1, W_f2, b_f2, out);
}

// round 17
// speedup vs baseline: 1.0997x; 1.0272x over previous
#include <cuda_runtime.h>
#include <cstdint>

#define NSN 50000
#define NDN 50000
#define EE  600000
#define CC  64
#define HH  8
#define LNEPS 1e-5f

typedef unsigned long long u64;

// packed f32x2 helpers (SASS FFMA2 — only reachable via PTX fma.rn.f32x2)
#define FFMA2(d, a, b, c) asm("fma.rn.f32x2 %0, %1, %2, %3;" : "=l"(d) : "l"(a), "l"(b), "l"(c))
#define MUL2(d, a, b)     asm("mul.rn.f32x2 %0, %1, %2;"     : "=l"(d) : "l"(a), "l"(b))
#define ADD2(d, a, b)     asm("add.rn.f32x2 %0, %1, %2;"     : "=l"(d) : "l"(a), "l"(b))
#define PK2(d, x)         asm("mov.b64 %0, {%1, %1};"        : "=l"(d) : "f"(x))
#define UPK2(lo, hi, v)   asm("mov.b64 {%0, %1}, %2;"        : "=f"(lo), "=f"(hi) : "l"(v))

// tf32 mma m16n8k8 (legacy HMMA path, sm_80+; sm_103-compatible)
#define MMA8(d, a, b0v, b1v) \
    asm volatile("mma.sync.aligned.m16n8k8.row.col.f32.tf32.tf32.f32 " \
        "{%0,%1,%2,%3},{%4,%5,%6,%7},{%8,%9},{%0,%1,%2,%3};" \
        : "+f"((d)[0]), "+f"((d)[1]), "+f"((d)[2]), "+f"((d)[3]) \
        : "r"((a)[0]), "r"((a)[1]), "r"((a)[2]), "r"((a)[3]), "r"(b0v), "r"(b1v))

__device__ __forceinline__ void tfsplit(float x, uint32_t& hi, uint32_t& lo) {
    uint32_t xb = __float_as_uint(x);
    hi = xb & 0xFFFFE000u;                       // truncate to tf32 mantissa
    lo = __float_as_uint(x - __uint_as_float(hi)); // exact residual (HW ignores low bits)
}

// ---------------- scratch ----------------
__device__ float g_ms[(size_t)NSN*CC];
__device__ float g_md[(size_t)NDN*CC];
__device__ float g_z[(size_t)NDN*HH];
__device__ float g_acc[(size_t)NDN*CC];

// ---------------- node projections: 512 threads, 128-node tiles, 2n x 8c ----------------
#define KN_SMEM 16960
#define SDN 132
__global__ void __launch_bounds__(512)
k_node(const float* __restrict__ src_f, const float* __restrict__ dst_f,
       const float* __restrict__ lnsw, const float* __restrict__ lnsb,
       const float* __restrict__ Wsrc,
       const float* __restrict__ lndw, const float* __restrict__ lndb,
       const float* __restrict__ Wdst, const float* __restrict__ bdst) {
    extern __shared__ float sn[];
    float* sW  = sn;
    float* sYt = sn + 8192;
    float* sBd = sn + 16640;
    float* sLn = sn + 16704;
    const int tid = threadIdx.x;
    for (int i = tid; i < 8192; i += 512) sW[i] = (i < 4096) ? Wsrc[i] : Wdst[i-4096];
    if (tid < 64) {
        sBd[tid] = bdst[tid];
        sLn[tid] = lnsw[tid]; sLn[64+tid] = lnsb[tid];
        sLn[128+tid] = lndw[tid]; sLn[192+tid] = lndb[tid];
    }
    const int NTS = (NSN + 127)/128, NTD = (NDN + 127)/128;
    const int lane = tid & 31, warp = tid >> 5;
    const int tc = warp & 7;
    const int n0 = ((warp >> 3) << 6) + lane*2;
    for (int tile = blockIdx.x; tile < NTS + NTD; tile += gridDim.x) {
        const bool isd = (tile >= NTS);
        const int base = (isd ? tile - NTS : tile) * 128;
        const int NV = isd ? NDN : NSN;
        __syncthreads();
        {
            const int n = tid >> 2, p = tid & 3;
            int gn = base + n; if (gn >= NV) gn = NV - 1;
            const float4* xr = (const float4*)((isd ? dst_f : src_f) + (size_t)gn*64 + p*16);
            float4 v[4]; float s = 0.f, q = 0.f;
            #pragma unroll
            for (int j = 0; j < 4; j++) {
                v[j] = xr[j];
                s += v[j].x + v[j].y + v[j].z + v[j].w;
                q += v[j].x*v[j].x + v[j].y*v[j].y + v[j].z*v[j].z + v[j].w*v[j].w;
            }
            s += __shfl_xor_sync(~0u, s, 1); s += __shfl_xor_sync(~0u, s, 2);
            q += __shfl_xor_sync(~0u, q, 1); q += __shfl_xor_sync(~0u, q, 2);
            const float mean = s * (1.0f/64.0f);
            const float var  = q * (1.0f/64.0f) - mean*mean;
            const float rs   = rsqrtf(var + LNEPS);
            const float* lw = sLn + (isd ? 128 : 0);
            const float* lb = sLn + (isd ? 192 : 64);
            #pragma unroll
            for (int j = 0; j < 4; j++) {
                const int k0 = p*16 + j*4;
                sYt[(k0+0)*SDN + n] = (v[j].x - mean)*rs*lw[k0+0] + lb[k0+0];
                sYt[(k0+1)*SDN + n] = (v[j].y - mean)*rs*lw[k0+1] + lb[k0+1];
                sYt[(k0+2)*SDN + n] = (v[j].z - mean)*rs*lw[k0+2] + lb[k0+2];
                sYt[(k0+3)*SDN + n] = (v[j].w - mean)*rs*lw[k0+3] + lb[k0+3];
            }
            if (isd && base + n < NDN) {
                float4 z = make_float4(0.f, 0.f, 0.f, 0.f);
                *(float4*)(g_acc + (size_t)(base + n)*64 + p*16)      = z;
                *(float4*)(g_acc + (size_t)(base + n)*64 + p*16 + 4)  = z;
                *(float4*)(g_acc + (size_t)(base + n)*64 + p*16 + 8)  = z;
                *(float4*)(g_acc + (size_t)(base + n)*64 + p*16 + 12) = z;
                *(float2*)(g_z + (size_t)(base + n)*8 + p*2) = make_float2(0.f, 0.f);
            }
        }
        __syncthreads();
        {
            const float* W = sW + (isd ? 4096 : 0);
            u64 acc[2][4] = {};
            #pragma unroll 4
            for (int k = 0; k < 64; k++) {
                float2 xv = *(const float2*)(sYt + k*SDN + n0);
                ulonglong2 wa = *(const ulonglong2*)(W + k*64 + tc*8);
                ulonglong2 wb = *(const ulonglong2*)(W + k*64 + tc*8 + 4);
                u64 xp;
                PK2(xp, xv.x);
                FFMA2(acc[0][0], xp, wa.x, acc[0][0]); FFMA2(acc[0][1], xp, wa.y, acc[0][1]);
                FFMA2(acc[0][2], xp, wb.x, acc[0][2]); FFMA2(acc[0][3], xp, wb.y, acc[0][3]);
                PK2(xp, xv.y);
                FFMA2(acc[1][0], xp, wa.x, acc[1][0]); FFMA2(acc[1][1], xp, wa.y, acc[1][1]);
                FFMA2(acc[1][2], xp, wb.x, acc[1][2]); FFMA2(acc[1][3], xp, wb.y, acc[1][3]);
            }
            float* outp = isd ? g_md : g_ms;
            #pragma unroll
            for (int i = 0; i < 2; i++) {
                const int gn = base + n0 + i;
                if (gn >= NV) continue;
                float4 o0, o1;
                UPK2(o0.x, o0.y, acc[i][0]); UPK2(o0.z, o0.w, acc[i][1]);
                UPK2(o1.x, o1.y, acc[i][2]); UPK2(o1.z, o1.w, acc[i][3]);
                if (isd) {
                    o0.x += sBd[tc*8+0]; o0.y += sBd[tc*8+1];
                    o0.z += sBd[tc*8+2]; o0.w += sBd[tc*8+3];
                    o1.x += sBd[tc*8+4]; o1.y += sBd[tc*8+5];
                    o1.z += sBd[tc*8+6]; o1.w += sBd[tc*8+7];
                }
                *(float4*)(outp + (size_t)gn*64 + tc*8)     = o0;
                *(float4*)(outp + (size_t)gn*64 + tc*8 + 4) = o1;
            }
        }
    }
}

// ---------------- edge kernel: scalar GEMM1/Gea + 3xTF32 HMMA GEMM2/3 ----------------
#define TEDGE 128
#define NTILE2 ((EE + TEDGE - 1) / TEDGE)
#define SDE 132
#define LDW 68
#define OFF_WR1    0
#define OFF_WEA    4096
#define OFF_WR2T   5120
#define OFF_WDTPT  13824
#define OFF_BR1    22528
#define OFF_BR2    22592
#define OFF_AL     22720
#define OFF_ESt    22784
#define OFF_Rt     (OFF_ESt + 8448)
#define OFF_MSGt   (OFF_Rt  + 8448)
#define OFF_EAt    (OFF_MSGt+ 8448)
#define SMEM_EDGE_FLOATS (OFF_EAt + 2112)

__global__ void __launch_bounds__(256, 1)
k_edge(const float* __restrict__ es_g, const float* __restrict__ ea_g,
       const float* __restrict__ el_g,
       const int* __restrict__ esrc, const int* __restrict__ edst,
       const float* __restrict__ Wr1, const float* __restrict__ br1,
       const float* __restrict__ Wr2, const float* __restrict__ br2,
       const float* __restrict__ Wea, const float* __restrict__ Wdtp,
       const float* __restrict__ alpha) {
    extern __shared__ float sm[];
    float* sWr1   = sm + OFF_WR1;
    float* sWea   = sm + OFF_WEA;
    float* sWr2T  = sm + OFF_WR2T;
    float* sWdtpT = sm + OFF_WDTPT;
    float* sbr1   = sm + OFF_BR1;
    float* sbr2   = sm + OFF_BR2;
    float* sal    = sm + OFF_AL;
    float* sESt   = sm + OFF_ESt;
    float* sRt    = sm + OFF_Rt;
    float* sMSGt  = sm + OFF_MSGt;
    float* sEAt   = sm + OFF_EAt;

    const int tid = threadIdx.x;
    for (int i = tid; i < 4096; i += 256) sWr1[i] = Wr1[i];
    for (int i = tid; i < 1024; i += 256) sWea[i] = Wea[i];
    for (int i = tid; i < 8192; i += 256) {
        int k = i >> 7, n = i & 127;
        sWr2T[n*LDW + k]  = Wr2[i];
        sWdtpT[n*LDW + k] = Wdtp[i];
    }
    if (tid < 64)  sbr1[tid] = br1[tid];
    if (tid < 128) sbr2[tid] = br2[tid];
    if (tid < 64)  sal[tid]  = alpha[tid];

    const int te = tid & 31;
    const int tc = tid >> 5;       // warp index: GEMM1 cols tc*8..+8; mma edges tc*16..+16
    const int e0 = te * 4;
    const int gid = te >> 2, tg = te & 3;
    const int mbg = tc*16 + gid;   // mma A row base for this thread

    const int e_st = tid >> 2, p_st = tid & 3;

    float4 pes[2][4];
    float4 pea[2];
#define PREFETCH_ES(t) do {                                                   \
        const int bb = (t) * TEDGE;                                           \
        int geA = bb + e_st;      if (geA >= EE) geA = EE - 1;                \
        int geB = bb + e_st + 64; if (geB >= EE) geB = EE - 1;                \
        const float4* rA = (const float4*)(es_g + (size_t)geA*64 + p_st*16);  \
        const float4* rB = (const float4*)(es_g + (size_t)geB*64 + p_st*16);  \
        pes[0][0]=rA[0]; pes[0][1]=rA[1]; pes[0][2]=rA[2]; pes[0][3]=rA[3];   \
        pes[1][0]=rB[0]; pes[1][1]=rB[1]; pes[1][2]=rB[2]; pes[1][3]=rB[3];   \
        pea[0] = *(const float4*)(ea_g + (size_t)geA*16 + p_st*4);            \
        pea[1] = *(const float4*)(ea_g + (size_t)geB*16 + p_st*4);            \
    } while (0)

    PREFETCH_ES(blockIdx.x);

    for (int tile = blockIdx.x; tile < NTILE2; tile += gridDim.x) {
        const int base = tile * TEDGE;
        __syncthreads();

        // ---- staging ----
        {
            float4 gms[2][4], gmd[2][4];
            #pragma unroll
            for (int j = 0; j < 2; j++) {
                const int e = e_st + j*64;
                int ge = base + e; if (ge >= EE) ge = EE - 1;
                const int sidx = esrc[ge], didx = edst[ge];
                const float4* msr = (const float4*)(g_ms + (size_t)sidx*64 + p_st*16);
                const float4* mdr = (const float4*)(g_md + (size_t)didx*64 + p_st*16);
                #pragma unroll
                for (int q = 0; q < 4; q++) { gms[j][q] = msr[q]; gmd[j][q] = mdr[q]; }
            }
            #pragma unroll
            for (int j = 0; j < 2; j++) {
                const int e = e_st + j*64;
                #pragma unroll
                for (int q = 0; q < 4; q++) {
                    const int k0 = p_st*16 + q*4;
                    sESt[(k0+0)*SDE + e] = pes[j][q].x;
                    sESt[(k0+1)*SDE + e] = pes[j][q].y;
                    sESt[(k0+2)*SDE + e] = pes[j][q].z;
                    sESt[(k0+3)*SDE + e] = pes[j][q].w;
                }
                const int ka = p_st*4;
                sEAt[(ka+0)*SDE + e] = pea[j].x;
                sEAt[(ka+1)*SDE + e] = pea[j].y;
                sEAt[(ka+2)*SDE + e] = pea[j].z;
                sEAt[(ka+3)*SDE + e] = pea[j].w;
            }
            #pragma unroll
            for (int j = 0; j < 2; j++) {
                const int e = e_st + j*64;
                #pragma unroll
                for (int q = 0; q < 4; q++) {
                    const int k0 = p_st*16 + q*4;
                    sMSGt[(k0+0)*SDE + e] = gms[j][q].x + gmd[j][q].x;
                    sMSGt[(k0+1)*SDE + e] = gms[j][q].y + gmd[j][q].y;
                    sMSGt[(k0+2)*SDE + e] = gms[j][q].z + gmd[j][q].z;
                    sMSGt[(k0+3)*SDE + e] = gms[j][q].w + gmd[j][q].w;
                }
            }
        }
        {
            int nt = tile + gridDim.x; if (nt >= NTILE2) nt = NTILE2 - 1;
            PREFETCH_ES(nt);
        }
        __syncthreads();

        // ---- GEMM1: r = silu(es @ Wr1 + br1) (scalar FFMA2) + Gea + T ----
        u64 ea2[4][4] = {};
        {
            u64 acc[4][4] = {};
            #pragma unroll 4
            for (int k = 0; k < 64; k++) {
                float4 xv = *(const float4*)(sESt + k*SDE + e0);
                ulonglong2 wa = *(const ulonglong2*)(sWr1 + k*64 + tc*8);
                ulonglong2 wb = *(const ulonglong2*)(sWr1 + k*64 + tc*8 + 4);
                u64 xp;
                PK2(xp, xv.x);
                FFMA2(acc[0][0], xp, wa.x, acc[0][0]); FFMA2(acc[0][1], xp, wa.y, acc[0][1]);
                FFMA2(acc[0][2], xp, wb.x, acc[0][2]); FFMA2(acc[0][3], xp, wb.y, acc[0][3]);
                PK2(xp, xv.y);
                FFMA2(acc[1][0], xp, wa.x, acc[1][0]); FFMA2(acc[1][1], xp, wa.y, acc[1][1]);
                FFMA2(acc[1][2], xp, wb.x, acc[1][2]); FFMA2(acc[1][3], xp, wb.y, acc[1][3]);
                PK2(xp, xv.z);
                FFMA2(acc[2][0], xp, wa.x, acc[2][0]); FFMA2(acc[2][1], xp, wa.y, acc[2][1]);
                FFMA2(acc[2][2], xp, wb.x, acc[2][2]); FFMA2(acc[2][3], xp, wb.y, acc[2][3]);
                PK2(xp, xv.w);
                FFMA2(acc[3][0], xp, wa.x, acc[3][0]); FFMA2(acc[3][1], xp, wa.y, acc[3][1]);
                FFMA2(acc[3][2], xp, wb.x, acc[3][2]); FFMA2(acc[3][3], xp, wb.y, acc[3][3]);
            }
            #pragma unroll
            for (int jp = 0; jp < 4; jp++) {
                float lo[4], hi[4];
                #pragma unroll
                for (int i = 0; i < 4; i++) UPK2(lo[i], hi[i], acc[i][jp]);
                float b0 = sbr1[tc*8 + 2*jp], b1 = sbr1[tc*8 + 2*jp + 1];
                float4 v0, v1;
                v0.x = lo[0]+b0; v0.y = lo[1]+b0; v0.z = lo[2]+b0; v0.w = lo[3]+b0;
                v1.x = hi[0]+b1; v1.y = hi[1]+b1; v1.z = hi[2]+b1; v1.w = hi[3]+b1;
                v0.x /= (1.0f + __expf(-v0.x)); v0.y /= (1.0f + __expf(-v0.y));
                v0.z /= (1.0f + __expf(-v0.z)); v0.w /= (1.0f + __expf(-v0.w));
                v1.x /= (1.0f + __expf(-v1.x)); v1.y /= (1.0f + __expf(-v1.y));
                v1.z /= (1.0f + __expf(-v1.z)); v1.w /= (1.0f + __expf(-v1.w));
                *(float4*)(sRt + (tc*8 + 2*jp)*SDE   + e0) = v0;
                *(float4*)(sRt + (tc*8 + 2*jp+1)*SDE + e0) = v1;
            }
            #pragma unroll
            for (int k = 0; k < 16; k++) {
                float4 xv = *(const float4*)(sEAt + k*SDE + e0);
                ulonglong2 wa = *(const ulonglong2*)(sWea + k*64 + tc*8);
                ulonglong2 wb = *(const ulonglong2*)(sWea + k*64 + tc*8 + 4);
                u64 xp;
                PK2(xp, xv.x);
                FFMA2(ea2[0][0], xp, wa.x, ea2[0][0]); FFMA2(ea2[0][1], xp, wa.y, ea2[0][1]);
                FFMA2(ea2[0][2], xp, wb.x, ea2[0][2]); FFMA2(ea2[0][3], xp, wb.y, ea2[0][3]);
                PK2(xp, xv.y);
                FFMA2(ea2[1][0], xp, wa.x, ea2[1][0]); FFMA2(ea2[1][1], xp, wa.y, ea2[1][1]);
                FFMA2(ea2[1][2], xp, wb.x, ea2[1][2]); FFMA2(ea2[1][3], xp, wb.y, ea2[1][3]);
                PK2(xp, xv.z);
                FFMA2(ea2[2][0], xp, wa.x, ea2[2][0]); FFMA2(ea2[2][1], xp, wa.y, ea2[2][1]);
                FFMA2(ea2[2][2], xp, wb.x, ea2[2][2]); FFMA2(ea2[2][3], xp, wb.y, ea2[2][3]);
                PK2(xp, xv.w);
                FFMA2(ea2[3][0], xp, wa.x, ea2[3][0]); FFMA2(ea2[3][1], xp, wa.y, ea2[3][1]);
                FFMA2(ea2[3][2], xp, wb.x, ea2[3][2]); FFMA2(ea2[3][3], xp, wb.y, ea2[3][3]);
            }
            #pragma unroll
            for (int jp = 0; jp < 4; jp++) {
                #pragma unroll
                for (int h = 0; h < 2; h++) {
                    const int c = tc*8 + 2*jp + h;
                    float4 m4 = *(float4*)(sMSGt + c*SDE + e0);
                    float v0, v1, v2, v3, dummy;
                    if (h == 0) {
                        UPK2(v0, dummy, ea2[0][jp]); UPK2(v1, dummy, ea2[1][jp]);
                        UPK2(v2, dummy, ea2[2][jp]); UPK2(v3, dummy, ea2[3][jp]);
                    } else {
                        UPK2(dummy, v0, ea2[0][jp]); UPK2(dummy, v1, ea2[1][jp]);
                        UPK2(dummy, v2, ea2[2][jp]); UPK2(dummy, v3, ea2[3][jp]);
                    }
                    m4.x *= v0; m4.y *= v1; m4.z *= v2; m4.w *= v3;
                    *(float4*)(sMSGt + c*SDE + e0) = m4;
                }
            }
        }
        __syncthreads();

        // ---- GEMM2 (r @ Wr2) via 3xTF32 mma: warp owns 16 edges x 128 cols ----
        float wef[16][4] = {};
        for (int kb = 0; kb < 64; kb += 8) {
            uint32_t ah[4], al[4];
            {
                float af0 = sRt[(kb+tg)*SDE + mbg];
                float af1 = sRt[(kb+tg)*SDE + mbg + 8];
                float af2 = sRt[(kb+tg+4)*SDE + mbg];
                float af3 = sRt[(kb+tg+4)*SDE + mbg + 8];
                tfsplit(af0, ah[0], al[0]); tfsplit(af1, ah[1], al[1]);
                tfsplit(af2, ah[2], al[2]); tfsplit(af3, ah[3], al[3]);
            }
            #pragma unroll
            for (int nt = 0; nt < 16; nt++) {
                float b0f = sWr2T[(nt*8+gid)*LDW + kb+tg];
                float b1f = sWr2T[(nt*8+gid)*LDW + kb+tg+4];
                uint32_t bh0, bl0, bh1, bl1;
                tfsplit(b0f, bh0, bl0); tfsplit(b1f, bh1, bl1);
                MMA8(wef[nt], ah, bh0, bh1);
                MMA8(wef[nt], ah, bl0, bl1);
                MMA8(wef[nt], al, bh0, bh1);
            }
        }

        // ---- GEMM3 (T @ Wdtp) via 3xTF32 mma ----
        float d3[16][4] = {};
        for (int kb = 0; kb < 64; kb += 8) {
            uint32_t ah[4], al[4];
            {
                float af0 = sMSGt[(kb+tg)*SDE + mbg];
                float af1 = sMSGt[(kb+tg)*SDE + mbg + 8];
                float af2 = sMSGt[(kb+tg+4)*SDE + mbg];
                float af3 = sMSGt[(kb+tg+4)*SDE + mbg + 8];
                tfsplit(af0, ah[0], al[0]); tfsplit(af1, ah[1], al[1]);
                tfsplit(af2, ah[2], al[2]); tfsplit(af3, ah[3], al[3]);
            }
            #pragma unroll
            for (int nt = 0; nt < 16; nt++) {
                float b0f = sWdtpT[(nt*8+gid)*LDW + kb+tg];
                float b1f = sWdtpT[(nt*8+gid)*LDW + kb+tg+4];
                uint32_t bh0, bl0, bh1, bl1;
                tfsplit(b0f, bh0, bl0); tfsplit(b1f, bh1, bl1);
                MMA8(d3[nt], ah, bh0, bh1);
                MMA8(d3[nt], ah, bl0, bl1);
                MMA8(d3[nt], al, bh0, bh1);
            }
        }

        // ---- dtp = d3 * (wef + br2), in-place into wef ----
        #pragma unroll
        for (int nt = 0; nt < 16; nt++) {
            float blo = sbr2[nt*8 + tg*2], bhi = sbr2[nt*8 + tg*2 + 1];
            wef[nt][0] = d3[nt][0] * (wef[nt][0] + blo);
            wef[nt][1] = d3[nt][1] * (wef[nt][1] + bhi);
            wef[nt][2] = d3[nt][2] * (wef[nt][2] + blo);
            wef[nt][3] = d3[nt][3] * (wef[nt][3] + bhi);
        }

        // ---- epilogue: fragment rows = edges mbg, mbg+8 ----
        {
            const int ge0 = base + mbg, ge1 = ge0 + 8;
            const int ge0c = (ge0 < EE) ? ge0 : EE-1;
            const int ge1c = (ge1 < EE) ? ge1 : EE-1;
            const float el0 = el_g[ge0c], el1 = el_g[ge1c];
            const int d0 = edst[ge0c], d1 = edst[ge1c];
            float ah0[8], ah1[8];
            #pragma unroll
            for (int h = 0; h < 8; h++) {
                const float s0 = sal[h*8 + tg*2], s1 = sal[h*8 + tg*2 + 1];
                float x0 = wef[h][0], x1 = wef[h][1];
                float y0 = wef[h][2], y1 = wef[h][3];
                float p0 = ((x0 > 0.f) ? x0 : 0.2f*x0)*s0 + ((x1 > 0.f) ? x1 : 0.2f*x1)*s1;
                float p1 = ((y0 > 0.f) ? y0 : 0.2f*y0)*s0 + ((y1 > 0.f) ? y1 : 0.2f*y1)*s1;
                p0 += __shfl_xor_sync(~0u, p0, 1); p0 += __shfl_xor_sync(~0u, p0, 2);
                p1 += __shfl_xor_sync(~0u, p1, 1); p1 += __shfl_xor_sync(~0u, p1, 2);
                float a0 = __expf(p0 + el0), a1 = __expf(p1 + el1);
                ah0[h] = a0; ah1[h] = a1;
                if (tg == 0) {
                    if (ge0 < EE)
                        asm volatile("red.global.add.f32 [%0], %1;"
                                     :: "l"(g_z + (size_t)d0*8 + h), "f"(a0) : "memory");
                    if (ge1 < EE)
                        asm volatile("red.global.add.f32 [%0], %1;"
                                     :: "l"(g_z + (size_t)d1*8 + h), "f"(a1) : "memory");
                }
            }
            #pragma unroll
            for (int h = 0; h < 8; h++) {
                const int nt = h + 8;
                if (ge0 < EE)
                    asm volatile("red.global.add.v2.f32 [%0], {%1,%2};"
                                 :: "l"(g_acc + (size_t)d0*64 + h*8 + tg*2),
                                    "f"(wef[nt][0]*ah0[h]), "f"(wef[nt][1]*ah0[h]) : "memory");
                if (ge1 < EE)
                    asm volatile("red.global.add.v2.f32 [%0], {%1,%2};"
                                 :: "l"(g_acc + (size_t)d1*64 + h*8 + tg*2),
                                    "f"(wef[nt][2]*ah1[h]), "f"(wef[nt][3]*ah1[h]) : "memory");
            }
        }
    }
}

// ---------------- final: 512 threads, 128-node tiles, 2n x 8c, fused FFN ----------------
#define FW_P   0
#define FW_1   4096
#define FW_2   16384
#define F_BP   28672
#define F_LNW  28736
#define F_LNB  28800
#define F_BF1  28864
#define F_BF2  29056
#define F_SS   29120
#define F_SQ   29248
#define F_XT   29376
#define F_YT   37824
#define SMEM_FIN 46272

__global__ void __launch_bounds__(512, 1)
k_final(const float* __restrict__ dst_f,
        const float* __restrict__ Wp, const float* __restrict__ bp,
        const float* __restrict__ lnw, const float* __restrict__ lnb,
        const float* __restrict__ Wf1, const float* __restrict__ bf1,
        const float* __restrict__ Wf2, const float* __restrict__ bf2,
        float* __restrict__ out) {
    extern __shared__ float sf[];
    const int tid = threadIdx.x;
    for (int i = tid; i < 4096;  i += 512) sf[FW_P + i] = Wp[i];
    for (int i = tid; i < 12288; i += 512) sf[FW_1 + i] = Wf1[i];
    for (int i = tid; i < 12288; i += 512) sf[FW_2 + i] = Wf2[i];
    if (tid < 64) {
        sf[F_BP  + tid] = bp[tid];
        sf[F_LNW + tid] = lnw[tid];
        sf[F_LNB + tid] = lnb[tid];
        sf[F_BF2 + tid] = bf2[tid];
    }
    if (tid < 192) sf[F_BF1 + tid] = bf1[tid];

    const int NT = (NDN + 127)/128;
    const int lane = tid & 31, warp = tid >> 5;
    const int tc = warp & 7;
    const int n0 = ((warp >> 3) << 6) + lane*2;

    for (int tile = blockIdx.x; tile < NT; tile += gridDim.x) {
        const int base = tile * 128;
        __syncthreads();
        if (tid < 128) { sf[F_SS + tid] = 0.0f; sf[F_SQ + tid] = 0.0f; }
        {
            const int n = tid >> 2, p = tid & 3;
            int gn = base + n; if (gn >= NDN) gn = NDN - 1;
            const float4* ar = (const float4*)(g_acc + (size_t)gn*64 + p*16);
            float z0 = g_z[(size_t)gn*8 + 2*p], z1 = g_z[(size_t)gn*8 + 2*p + 1];
            float r0 = (z0 > 0.0f) ? 1.0f/z0 : 0.0f;
            float r1 = (z1 > 0.0f) ? 1.0f/z1 : 0.0f;
            #pragma unroll
            for (int j = 0; j < 4; j++) {
                float4 v = ar[j];
                const float rr = (j < 2) ? r0 : r1;
                const int k0 = p*16 + j*4;
                sf[F_XT + (k0+0)*SDN + n] = v.x * rr;
                sf[F_XT + (k0+1)*SDN + n] = v.y * rr;
                sf[F_XT + (k0+2)*SDN + n] = v.z * rr;
                sf[F_XT + (k0+3)*SDN + n] = v.w * rr;
            }
        }
        __syncthreads();

        float emb[2][8];
        {
            u64 acc[2][4] = {};
            #pragma unroll 4
            for (int k = 0; k < 64; k++) {
                float2 xv = *(const float2*)(sf + F_XT + k*SDN + n0);
                ulonglong2 wa = *(const ulonglong2*)(sf + FW_P + k*64 + tc*8);
                ulonglong2 wb = *(const ulonglong2*)(sf + FW_P + k*64 + tc*8 + 4);
                u64 xp;
                PK2(xp, xv.x);
                FFMA2(acc[0][0], xp, wa.x, acc[0][0]); FFMA2(acc[0][1], xp, wa.y, acc[0][1]);
                FFMA2(acc[0][2], xp, wb.x, acc[0][2]); FFMA2(acc[0][3], xp, wb.y, acc[0][3]);
                PK2(xp, xv.y);
                FFMA2(acc[1][0], xp, wa.x, acc[1][0]); FFMA2(acc[1][1], xp, wa.y, acc[1][1]);
                FFMA2(acc[1][2], xp, wb.x, acc[1][2]); FFMA2(acc[1][3], xp, wb.y, acc[1][3]);
            }
            #pragma unroll
            for (int i = 0; i < 2; i++) {
                int gn = base + n0 + i; if (gn >= NDN) gn = NDN - 1;
                float4 d0 = *(const float4*)(dst_f + (size_t)gn*64 + tc*8);
                float4 d1 = *(const float4*)(dst_f + (size_t)gn*64 + tc*8 + 4);
                UPK2(emb[i][0], emb[i][1], acc[i][0]);
                UPK2(emb[i][2], emb[i][3], acc[i][1]);
                UPK2(emb[i][4], emb[i][5], acc[i][2]);
                UPK2(emb[i][6], emb[i][7], acc[i][3]);
                emb[i][0] += sf[F_BP + tc*8+0] + d0.x;
                emb[i][1] += sf[F_BP + tc*8+1] + d0.y;
                emb[i][2] += sf[F_BP + tc*8+2] + d0.z;
                emb[i][3] += sf[F_BP + tc*8+3] + d0.w;
                emb[i][4] += sf[F_BP + tc*8+4] + d1.x;
                emb[i][5] += sf[F_BP + tc*8+5] + d1.y;
                emb[i][6] += sf[F_BP + tc*8+6] + d1.z;
                emb[i][7] += sf[F_BP + tc*8+7] + d1.w;
            }
            #pragma unroll
            for (int i = 0; i < 2; i++) {
                float s = 0.f, q = 0.f;
                #pragma unroll
                for (int j = 0; j < 8; j++) { s += emb[i][j]; q += emb[i][j]*emb[i][j]; }
                atomicAdd(sf + F_SS + n0 + i, s);
                atomicAdd(sf + F_SQ + n0 + i, q);
            }
        }
        __syncthreads();

        {
            float mean[2], rs[2];
            #pragma unroll
            for (int i = 0; i < 2; i++) {
                mean[i] = sf[F_SS + n0 + i] * (1.0f/64.0f);
                float var = sf[F_SQ + n0 + i] * (1.0f/64.0f) - mean[i]*mean[i];
                rs[i] = rsqrtf(var + LNEPS);
            }
            #pragma unroll
            for (int j = 0; j < 8; j++) {
                const int c = tc*8 + j;
                const float lw = sf[F_LNW + c], lb = sf[F_LNB + c];
                float2 v;
                v.x = (emb[0][j] - mean[0]) * rs[0] * lw + lb;
                v.y = (emb[1][j] - mean[1]) * rs[1] * lw + lb;
                *(float2*)(sf + F_YT + c*SDN + n0) = v;
            }
        }
        __syncthreads();

        u64 oacc[2][4] = {};
        #pragma unroll
        for (int pp = 0; pp < 3; pp++) {
            {
                u64 acc[2][4] = {};
                #pragma unroll 4
                for (int k = 0; k < 64; k++) {
                    float2 xv = *(const float2*)(sf + F_YT + k*SDN + n0);
                    ulonglong2 wa = *(const ulonglong2*)(sf + FW_1 + k*192 + pp*64 + tc*8);
                    ulonglong2 wb = *(const ulonglong2*)(sf + FW_1 + k*192 + pp*64 + tc*8 + 4);
                    u64 xp;
                    PK2(xp, xv.x);
                    FFMA2(acc[0][0], xp, wa.x, acc[0][0]); FFMA2(acc[0][1], xp, wa.y, acc[0][1]);
                    FFMA2(acc[0][2], xp, wb.x, acc[0][2]); FFMA2(acc[0][3], xp, wb.y, acc[0][3]);
                    PK2(xp, xv.y);
                    FFMA2(acc[1][0], xp, wa.x, acc[1][0]); FFMA2(acc[1][1], xp, wa.y, acc[1][1]);
                    FFMA2(acc[1][2], xp, wb.x, acc[1][2]); FFMA2(acc[1][3], xp, wb.y, acc[1][3]);
                }
                float h[2][8];
                #pragma unroll
                for (int i = 0; i < 2; i++) {
                    UPK2(h[i][0], h[i][1], acc[i][0]);
                    UPK2(h[i][2], h[i][3], acc[i][1]);
                    UPK2(h[i][4], h[i][5], acc[i][2]);
                    UPK2(h[i][6], h[i][7], acc[i][3]);
                    #pragma unroll
                    for (int j = 0; j < 8; j++) {
                        float x = h[i][j] + sf[F_BF1 + pp*64 + tc*8 + j];
                        h[i][j] = x / (1.0f + __expf(-x));
                    }
                }
                #pragma unroll
                for (int j = 0; j < 8; j++) {
                    float2 v = make_float2(h[0][j], h[1][j]);
                    *(float2*)(sf + F_XT + (tc*8 + j)*SDN + n0) = v;
                }
            }
            __syncthreads();
            {
                #pragma unroll 4
                for (int k = 0; k < 64; k++) {
                    float2 xv = *(const float2*)(sf + F_XT + k*SDN + n0);
                    ulonglong2 wa = *(const ulonglong2*)(sf + FW_2 + (pp*64 + k)*64 + tc*8);
                    ulonglong2 wb = *(const ulonglong2*)(sf + FW_2 + (pp*64 + k)*64 + tc*8 + 4);
                    u64 xp;
                    PK2(xp, xv.x);
                    FFMA2(oacc[0][0], xp, wa.x, oacc[0][0]); FFMA2(oacc[0][1], xp, wa.y, oacc[0][1]);
                    FFMA2(oacc[0][2], xp, wb.x, oacc[0][2]); FFMA2(oacc[0][3], xp, wb.y, oacc[0][3]);
                    PK2(xp, xv.y);
                    FFMA2(oacc[1][0], xp, wa.x, oacc[1][0]); FFMA2(oacc[1][1], xp, wa.y, oacc[1][1]);
                    FFMA2(oacc[1][2], xp, wb.x, oacc[1][2]); FFMA2(oacc[1][3], xp, wb.y, oacc[1][3]);
                }
            }
            if (pp < 2) __syncthreads();
        }

        #pragma unroll
        for (int i = 0; i < 2; i++) {
            const int gn = base + n0 + i;
            if (gn >= NDN) continue;
            float o[8];
            UPK2(o[0], o[1], oacc[i][0]); UPK2(o[2], o[3], oacc[i][1]);
            UPK2(o[4], o[5], oacc[i][2]); UPK2(o[6], o[7], oacc[i][3]);
            float4 v0, v1;
            v0.x = o[0] + sf[F_BF2 + tc*8+0] + emb[i][0];
            v0.y = o[1] + sf[F_BF2 + tc*8+1] + emb[i][1];
            v0.z = o[2] + sf[F_BF2 + tc*8+2] + emb[i][2];
            v0.w = o[3] + sf[F_BF2 + tc*8+3] + emb[i][3];
            v1.x = o[4] + sf[F_BF2 + tc*8+4] + emb[i][4];
            v1.y = o[5] + sf[F_BF2 + tc*8+5] + emb[i][5];
            v1.z = o[6] + sf[F_BF2 + tc*8+6] + emb[i][6];
            v1.w = o[7] + sf[F_BF2 + tc*8+7] + emb[i][7];
            *(float4*)(out + (size_t)gn*64 + tc*8)     = v0;
            *(float4*)(out + (size_t)gn*64 + tc*8 + 4) = v1;
        }
    }
}

// ---------------- launch ----------------
extern "C" void kernel_launch(void* const* d_in, const int* in_sizes, int n_in,
                              void* d_out, int out_size) {
    const float* src_f        = (const float*)d_in[0];
    const float* dst_f        = (const float*)d_in[1];
    const float* edge_attr    = (const float*)d_in[2];
    const float* edge_scalars = (const float*)d_in[3];
    const float* edge_logits  = (const float*)d_in[4];
    const int*   edge_src     = (const int*)d_in[5];
    const int*   edge_dst     = (const int*)d_in[6];
    const float* ln_src_w = (const float*)d_in[7];
    const float* ln_src_b = (const float*)d_in[8];
    const float* W_src    = (const float*)d_in[9];
    const float* ln_dst_w = (const float*)d_in[10];
    const float* ln_dst_b = (const float*)d_in[11];
    const float* W_dst    = (const float*)d_in[12];
    const float* b_dst    = (const float*)d_in[13];
    const float* W_ea     = (const float*)d_in[14];
    const float* W_dtp    = (const float*)d_in[15];
    const float* W_r1     = (const float*)d_in[16];
    const float* b_r1     = (const float*)d_in[17];
    const float* W_r2     = (const float*)d_in[18];
    const float* b_r2     = (const float*)d_in[19];
    const float* alpha    = (const float*)d_in[20];
    const float* W_proj   = (const float*)d_in[21];
    const float* b_proj   = (const float*)d_in[22];
    const float* ln_post_w = (const float*)d_in[23];
    const float* ln_post_b = (const float*)d_in[24];
    const float* W_f1     = (const float*)d_in[25];
    const float* b_f1     = (const float*)d_in[26];
    const float* W_f2     = (const float*)d_in[27];
    const float* b_f2     = (const float*)d_in[28];
    float* out = (float*)d_out;

    cudaFuncSetAttribute(k_edge, cudaFuncAttributeMaxDynamicSharedMemorySize,
                         SMEM_EDGE_FLOATS * 4);
    cudaFuncSetAttribute(k_final, cudaFuncAttributeMaxDynamicSharedMemorySize,
                         SMEM_FIN * 4);
    cudaFuncSetAttribute(k_node, cudaFuncAttributeMaxDynamicSharedMemorySize,
                         KN_SMEM * 4);

    k_node<<<296, 512, KN_SMEM*4>>>(src_f, dst_f, ln_src_w, ln_src_b, W_src,
                                    ln_dst_w, ln_dst_b, W_dst, b_dst);
    k_edge<<<296, 256, SMEM_EDGE_FLOATS*4>>>(edge_scalars, edge_attr, edge_logits,
                                             edge_src, edge_dst,
                                             W_r1, b_r1, W_r2, b_r2, W_ea, W_dtp, alpha);
    k_final<<<148, 512, SMEM_FIN*4>>>(dst_f, W_proj, b_proj,
                                      ln_post_w, ln_post_b,
                                      W_f1, b_f1, W_f2, b_f2, out);
}